// round 11
// baseline (speedup 1.0000x reference)
#include <cuda_runtime.h>
#include <math.h>

// ---------------- problem constants ----------------
#define BN     8
#define NN     1024
#define DD     512
#define HH     8
#define DHD    64
#define NHASH  4
#define NBUCK  256
#define BSZ    4
#define BHN    (BN*HH)
#define MTOT   (BN*NN)
#define CHTOT  (NHASH*NBUCK)

typedef unsigned long long ull;

// ---- packed f32x2 helpers (FFMA2; bit-exact fp32, 2 lanes/instr) -----------
__device__ __forceinline__ ull pack2(float lo, float hi) {
    ull r; asm("mov.b64 %0, {%1, %2};" : "=l"(r) : "f"(lo), "f"(hi)); return r;
}
__device__ __forceinline__ void unpack2(ull v, float& lo, float& hi) {
    asm("mov.b64 {%0, %1}, %2;" : "=f"(lo), "=f"(hi) : "l"(v));
}
__device__ __forceinline__ void fma2(ull& d, ull a, ull b) {
    asm("fma.rn.f32x2 %0, %1, %2, %0;" : "+l"(d) : "l"(a), "l"(b));
}

// ---- 3xTF32 helpers --------------------------------------------------------
__device__ __forceinline__ void tf32_split(float x, unsigned& hi, unsigned& lo) {
    unsigned h; asm("cvt.rna.tf32.f32 %0, %1;" : "=r"(h) : "f"(x));
    float r = x - __uint_as_float(h);
    unsigned l; asm("cvt.rna.tf32.f32 %0, %1;" : "=r"(l) : "f"(r));
    hi = h; lo = l;
}
__device__ __forceinline__ void mma_tf32(float* c, const unsigned* a, const unsigned* b) {
    asm volatile("mma.sync.aligned.m16n8k8.row.col.f32.tf32.tf32.f32 "
        "{%0,%1,%2,%3}, {%4,%5,%6,%7}, {%8,%9}, {%0,%1,%2,%3};"
        : "+f"(c[0]), "+f"(c[1]), "+f"(c[2]), "+f"(c[3])
        : "r"(a[0]), "r"(a[1]), "r"(a[2]), "r"(a[3]), "r"(b[0]), "r"(b[1]));
}

// ---------------- scratch ---------------------------------------------------
__device__ float    g_qk    [BN*NN*DD];
__device__ float    g_v     [BN*NN*DD];
__device__ int      g_bucket[BHN*NHASH*NN];
__device__ int      g_st    [BHN*NHASH*NN];
__device__ float    g_o     [(size_t)BHN*NHASH*NN*DHD];
__device__ float    g_logits[BHN*NHASH*NN];
__device__ float    g_att   [BN*NN*DD];
// pre-split tf32 operands (perm-k layout). g_sh/g_sl shared by queries then att.
__device__ unsigned g_sh [MTOT*DD];
__device__ unsigned g_sl [MTOT*DD];
__device__ unsigned g_wvh[DD*DD];
__device__ unsigned g_wvl[DD*DD];
__device__ unsigned g_woh[DD*DD];
__device__ unsigned g_wol[DD*DD];

// perm within a k8 group: pos p holds k = (p>>1) + 4*(p&1)
// (so a uint2 at pos 2c,2c+1 = k-pair (c, c+4), matching the mma fragment)

// ---------------- prep: split row-major [rows][512] into perm hi/lo ---------
__global__ __launch_bounds__(256) void split_rows(
    const float* __restrict__ src, unsigned* __restrict__ hi, unsigned* __restrict__ lo)
{
    int id = blockIdx.x * 256 + threadIdx.x;      // rows*64 threads
    int row = id >> 6, kg = id & 63;
    const float* s = src + (size_t)row * DD + kg * 8;
    float4 v0 = *(const float4*)s;
    float4 v1 = *(const float4*)(s + 4);
    float f[8] = {v0.x, v0.y, v0.z, v0.w, v1.x, v1.y, v1.z, v1.w};
    unsigned oh[8], ol[8];
    #pragma unroll
    for (int p = 0; p < 8; p++) {
        int k = (p >> 1) + 4 * (p & 1);
        tf32_split(f[k], oh[p], ol[p]);
    }
    size_t off = (size_t)row * DD + kg * 8;
    *(uint4*)(hi + off)     = make_uint4(oh[0], oh[1], oh[2], oh[3]);
    *(uint4*)(hi + off + 4) = make_uint4(oh[4], oh[5], oh[6], oh[7]);
    *(uint4*)(lo + off)     = make_uint4(ol[0], ol[1], ol[2], ol[3]);
    *(uint4*)(lo + off + 4) = make_uint4(ol[4], ol[5], ol[6], ol[7]);
}

// ---------------- prep: split W[k][n] -> [n][perm k] hi/lo ------------------
__global__ __launch_bounds__(256) void split_w(
    const float* __restrict__ w, unsigned* __restrict__ hi, unsigned* __restrict__ lo)
{
    int id = blockIdx.x * 256 + threadIdx.x;      // 64*512 threads
    int kg = id >> 9, n = id & 511;
    float f[8];
    #pragma unroll
    for (int kw = 0; kw < 8; kw++)
        f[kw] = w[(size_t)(kg * 8 + kw) * DD + n];
    unsigned oh[8], ol[8];
    #pragma unroll
    for (int p = 0; p < 8; p++) {
        int k = (p >> 1) + 4 * (p & 1);
        tf32_split(f[k], oh[p], ol[p]);
    }
    size_t off = (size_t)n * DD + kg * 8;
    *(uint4*)(hi + off)     = make_uint4(oh[0], oh[1], oh[2], oh[3]);
    *(uint4*)(hi + off + 4) = make_uint4(oh[4], oh[5], oh[6], oh[7]);
    *(uint4*)(lo + off)     = make_uint4(ol[0], ol[1], ol[2], ol[3]);
    *(uint4*)(lo + off + 4) = make_uint4(ol[4], ol[5], ol[6], ol[7]);
}

// ---------------- K1 (qk): SGEMM 128x128, BK=8, FFMA2 (proven R6 version) ---
template<bool HASBIAS>
__global__ __launch_bounds__(256, 2) void sgemm128(
    const float* __restrict__ A, const float* __restrict__ Bm,
    const float* __restrict__ bias, float* __restrict__ C,
    int M, int Nn, int K)
{
    __shared__ __align__(16) float As[2][8][132];
    __shared__ __align__(16) float Bs[2][8][132];
    int tid = threadIdx.x;
    int bm = blockIdx.y * 128, bn = blockIdx.x * 128;
    int ty = tid >> 4, tx = tid & 15;

    int arow = tid >> 1;
    int akq  = (tid & 1) * 4;
    int bk   = tid >> 5;
    int bnq  = (tid & 31) * 4;

    const float* Aptr = A  + (size_t)(bm + arow) * K + akq;
    const float* Bptr = Bm + (size_t)bk * Nn + bn + bnq;

    ull acc[8][4];
    #pragma unroll
    for (int i = 0; i < 8; i++)
        #pragma unroll
        for (int jp = 0; jp < 4; jp++) acc[i][jp] = 0ull;

    float4 av = *(const float4*)(Aptr);
    float4 bv = *(const float4*)(Bptr);
    As[0][akq+0][arow] = av.x;
    As[0][akq+1][arow] = av.y;
    As[0][akq+2][arow] = av.z;
    As[0][akq+3][arow] = av.w;
    *(float4*)&Bs[0][bk][bnq] = bv;
    __syncthreads();

    int buf = 0;
    for (int k0 = 8; k0 <= K; k0 += 8) {
        if (k0 < K) {
            av = *(const float4*)(Aptr + k0);
            bv = *(const float4*)(Bptr + (size_t)k0 * Nn);
        }
        #pragma unroll
        for (int k = 0; k < 8; k++) {
            float4 a0 = *(const float4*)&As[buf][k][ty*4];
            float4 a1 = *(const float4*)&As[buf][k][64 + ty*4];
            ulonglong2 b0 = *(const ulonglong2*)&Bs[buf][k][tx*4];
            ulonglong2 b1 = *(const ulonglong2*)&Bs[buf][k][64 + tx*4];
            ull ad[8];
            ad[0] = pack2(a0.x, a0.x); ad[1] = pack2(a0.y, a0.y);
            ad[2] = pack2(a0.z, a0.z); ad[3] = pack2(a0.w, a0.w);
            ad[4] = pack2(a1.x, a1.x); ad[5] = pack2(a1.y, a1.y);
            ad[6] = pack2(a1.z, a1.z); ad[7] = pack2(a1.w, a1.w);
            #pragma unroll
            for (int i = 0; i < 8; i++) {
                fma2(acc[i][0], ad[i], b0.x);
                fma2(acc[i][1], ad[i], b0.y);
                fma2(acc[i][2], ad[i], b1.x);
                fma2(acc[i][3], ad[i], b1.y);
            }
        }
        if (k0 < K) {
            buf ^= 1;
            As[buf][akq+0][arow] = av.x;
            As[buf][akq+1][arow] = av.y;
            As[buf][akq+2][arow] = av.z;
            As[buf][akq+3][arow] = av.w;
            *(float4*)&Bs[buf][bk][bnq] = bv;
            __syncthreads();
        }
    }

    #pragma unroll
    for (int rh = 0; rh < 2; rh++)
        #pragma unroll
        for (int i = 0; i < 4; i++) {
            int row = bm + rh*64 + ty*4 + i;
            #pragma unroll
            for (int ch = 0; ch < 2; ch++) {
                float4 o;
                unpack2(acc[rh*4+i][ch*2+0], o.x, o.y);
                unpack2(acc[rh*4+i][ch*2+1], o.z, o.w);
                int col = bn + ch*64 + tx*4;
                if (HASBIAS) {
                    o.x += bias[col+0]; o.y += bias[col+1];
                    o.z += bias[col+2]; o.w += bias[col+3];
                }
                *(float4*)(C + (size_t)row * Nn + col) = o;
            }
        }
}

// ---------------- K1b (v, out): 3xTF32 TC GEMM, pre-split, double-buffered --
// Block 128x128, 256 thr (8 warps 2x4), warp tile 64x32, BK=8, K=512 fixed.
// smem stride 8 u32 (no pad): staging STS.128 and frag LDS.64 conflict-free
// (grp 0-3 / 4-7 land in separate phases).
template<bool HASBIAS>
__global__ __launch_bounds__(256, 2) void gemm_tc(
    const unsigned* __restrict__ Ahg, const unsigned* __restrict__ Alg,
    const unsigned* __restrict__ Bhg, const unsigned* __restrict__ Blg,
    const float* __restrict__ bias, float* __restrict__ C)
{
    __shared__ unsigned sAh[2][128][8], sAl[2][128][8];
    __shared__ unsigned sBh[2][128][8], sBl[2][128][8];
    int tid = threadIdx.x;
    int bm = blockIdx.y * 128, bn = blockIdx.x * 128;
    int wid = tid >> 5, lane = tid & 31;
    int m0 = (wid >> 2) * 64, n0 = (wid & 3) * 32;
    int grp = lane >> 2, cc = lane & 3;

    // staging map: each thread owns half a row (uint4) of each tile
    int sr = tid >> 1, pp = (tid & 1) * 4;
    const unsigned* pAh = Ahg + (size_t)(bm + sr) * DD + pp;
    const unsigned* pAl = Alg + (size_t)(bm + sr) * DD + pp;
    const unsigned* pBh = Bhg + (size_t)(bn + sr) * DD + pp;
    const unsigned* pBl = Blg + (size_t)(bn + sr) * DD + pp;

    float acc[4][4][4];
    #pragma unroll
    for (int t = 0; t < 4; t++)
        #pragma unroll
        for (int u = 0; u < 4; u++)
            #pragma unroll
            for (int x = 0; x < 4; x++) acc[t][u][x] = 0.f;

    // prologue: tile 0
    uint4 vah = *(const uint4*)(pAh);
    uint4 val = *(const uint4*)(pAl);
    uint4 vbh = *(const uint4*)(pBh);
    uint4 vbl = *(const uint4*)(pBl);
    *(uint4*)&sAh[0][sr][pp] = vah;
    *(uint4*)&sAl[0][sr][pp] = val;
    *(uint4*)&sBh[0][sr][pp] = vbh;
    *(uint4*)&sBl[0][sr][pp] = vbl;
    __syncthreads();

    int buf = 0;
    for (int kt = 1; kt <= 64; kt++) {
        if (kt < 64) {
            vah = *(const uint4*)(pAh + kt * 8);
            val = *(const uint4*)(pAl + kt * 8);
            vbh = *(const uint4*)(pBh + kt * 8);
            vbl = *(const uint4*)(pBl + kt * 8);
        }
        // B fragments for all u
        uint2 bfh[4], bfl[4];
        #pragma unroll
        for (int u = 0; u < 4; u++) {
            int nr = n0 + u*8 + grp;
            bfh[u] = *(const uint2*)&sBh[buf][nr][2*cc];
            bfl[u] = *(const uint2*)&sBl[buf][nr][2*cc];
        }
        #pragma unroll
        for (int t = 0; t < 4; t++) {
            int r0 = m0 + t*16 + grp;
            uint2 h0 = *(const uint2*)&sAh[buf][r0  ][2*cc];
            uint2 h1 = *(const uint2*)&sAh[buf][r0+8][2*cc];
            uint2 l0 = *(const uint2*)&sAl[buf][r0  ][2*cc];
            uint2 l1 = *(const uint2*)&sAl[buf][r0+8][2*cc];
            unsigned afh[4] = {h0.x, h1.x, h0.y, h1.y};
            unsigned afl[4] = {l0.x, l1.x, l0.y, l1.y};
            #pragma unroll
            for (int u = 0; u < 4; u++) {
                unsigned bh2[2] = {bfh[u].x, bfh[u].y};
                unsigned bl2[2] = {bfl[u].x, bfl[u].y};
                mma_tf32(acc[t][u], afl, bh2);   // Al*Bb
                mma_tf32(acc[t][u], afh, bl2);   // Ab*Bl
                mma_tf32(acc[t][u], afh, bh2);   // Ab*Bb
            }
        }
        if (kt < 64) {
            buf ^= 1;
            *(uint4*)&sAh[buf][sr][pp] = vah;
            *(uint4*)&sAl[buf][sr][pp] = val;
            *(uint4*)&sBh[buf][sr][pp] = vbh;
            *(uint4*)&sBl[buf][sr][pp] = vbl;
            __syncthreads();
        }
    }

    #pragma unroll
    for (int t = 0; t < 4; t++)
        #pragma unroll
        for (int u = 0; u < 4; u++) {
            int row = bm + m0 + t*16 + grp;
            int col = bn + n0 + u*8 + 2*cc;
            float2 o0 = make_float2(acc[t][u][0], acc[t][u][1]);
            float2 o1 = make_float2(acc[t][u][2], acc[t][u][3]);
            if (HASBIAS) {
                float2 bv = *(const float2*)(bias + col);
                o0.x += bv.x; o0.y += bv.y; o1.x += bv.x; o1.y += bv.y;
            }
            *(float2*)(C + (size_t)row * DD + col)       = o0;
            *(float2*)(C + (size_t)(row + 8) * DD + col) = o1;
        }
}

// ---------------- K2: LSH hashing, FFMA2 (bitwise-stable buckets) -----------
__global__ __launch_bounds__(128) void hash_kernel(const float* __restrict__ rot)
{
    __shared__ __align__(16) float qs[64][64];
    __shared__ __align__(16) float rs[64][128];
    int bh = blockIdx.y;
    int t0 = blockIdx.x * 64;
    int b = bh >> 3, h = bh & 7;
    int tid = threadIdx.x;
    int quad = tid >> 3, ig = tid & 7;

    for (int idx = tid; idx < 64*16; idx += 128) {
        int tk = idx >> 4, fq = (idx & 15) * 4;
        *(float4*)&qs[tk][fq] =
            *(const float4*)(g_qk + ((size_t)(b*NN + t0 + tk))*DD + h*DHD + fq);
    }

    for (int r = 0; r < NHASH; r++) {
        __syncthreads();
        for (int idx = tid; idx < 64*32; idx += 128) {
            int f = idx >> 5, iq = (idx & 31) * 4;
            *(float4*)&rs[f][iq] = *(const float4*)(rot + f*(NHASH*128) + r*128 + iq);
        }
        __syncthreads();

        ull acc2[4][4][2];
        #pragma unroll
        for (int tt = 0; tt < 4; tt++)
            #pragma unroll
            for (int c = 0; c < 4; c++) {
                acc2[tt][c][0] = 0ull; acc2[tt][c][1] = 0ull;
            }

        for (int f = 0; f < 64; f++) {
            ull qd[4];
            #pragma unroll
            for (int tt = 0; tt < 4; tt++) {
                float q = qs[quad*4 + tt][f];
                qd[tt] = pack2(q, q);
            }
            #pragma unroll
            for (int c = 0; c < 4; c++) {
                ulonglong2 rv = *(const ulonglong2*)&rs[f][ig*4 + c*32];
                #pragma unroll
                for (int tt = 0; tt < 4; tt++) {
                    fma2(acc2[tt][c][0], qd[tt], rv.x);
                    fma2(acc2[tt][c][1], qd[tt], rv.y);
                }
            }
        }

        #pragma unroll
        for (int tt = 0; tt < 4; tt++) {
            float bvv = -1e30f; int bi = 256;
            #pragma unroll
            for (int c = 0; c < 4; c++)
                #pragma unroll
                for (int jp = 0; jp < 2; jp++) {
                    float v0, v1;
                    unpack2(acc2[tt][c][jp], v0, v1);
                    float vv[2] = {v0, v1};
                    #pragma unroll
                    for (int u = 0; u < 2; u++) {
                        int i = ig*4 + c*32 + jp*2 + u;
                        float v = vv[u];
                        if (v > bvv || (v == bvv && i < bi)) { bvv = v; bi = i; }
                        float vn = -v; int i2 = 128 + i;
                        if (vn > bvv || (vn == bvv && i2 < bi)) { bvv = vn; bi = i2; }
                    }
                }
            #pragma unroll
            for (int m = 1; m < 8; m <<= 1) {
                float ov = __shfl_xor_sync(0xffffffffu, bvv, m);
                int   oi = __shfl_xor_sync(0xffffffffu, bi, m);
                if (ov > bvv || (ov == bvv && oi < bi)) { bvv = ov; bi = oi; }
            }
            if (ig == 0)
                g_bucket[(bh*NHASH + r)*NN + t0 + quad*4 + tt] = bi;
        }
    }
}

// ---------------- K3: stable counting sort per (bh, round) ------------------
__global__ __launch_bounds__(256) void sort_kernel()
{
    __shared__ __align__(16) int bks[NN];
    __shared__ int tmp[NN];
    __shared__ int hist[NBUCK];
    __shared__ int offs[NBUCK];
    __shared__ int cnt[NBUCK];
    __shared__ int wsum[8];
    int bhr = blockIdx.x;
    int tid = threadIdx.x;
    for (int t = tid; t < NN; t += 256) bks[t] = g_bucket[bhr*NN + t];
    hist[tid] = 0; cnt[tid] = 0;
    __syncthreads();
    for (int t = tid; t < NN; t += 256) atomicAdd(&hist[bks[t]], 1);
    __syncthreads();
    int hv = hist[tid];
    int incl = hv;
    #pragma unroll
    for (int d = 1; d < 32; d <<= 1) {
        int nv = __shfl_up_sync(0xffffffffu, incl, d);
        if ((tid & 31) >= d) incl += nv;
    }
    if ((tid & 31) == 31) wsum[tid >> 5] = incl;
    __syncthreads();
    if (tid == 0) {
        int s = 0;
        #pragma unroll
        for (int k = 0; k < 8; k++) { int t = wsum[k]; wsum[k] = s; s += t; }
    }
    __syncthreads();
    offs[tid] = incl - hv + wsum[tid >> 5];
    __syncthreads();
    for (int t = tid; t < NN; t += 256) {
        int b = bks[t];
        int p = atomicAdd(&cnt[b], 1);
        tmp[offs[b] + p] = t;
    }
    __syncthreads();
    {
        int o = offs[tid], k = hist[tid];
        for (int x = 1; x < k; x++) {
            int key = tmp[o + x];
            int y = x - 1;
            while (y >= 0 && tmp[o + y] > key) { tmp[o + y + 1] = tmp[o + y]; y--; }
            tmp[o + y + 1] = key;
        }
    }
    __syncthreads();
    for (int t = tid; t < NN; t += 256) g_st[bhr*NN + t] = tmp[t];
}

// ---------------- K4: chunked attention, lane-pair layout -------------------
__global__ __launch_bounds__(128) void attn_kernel()
{
    __shared__ __align__(16) float qs[4][4][68];
    __shared__ __align__(16) float ks[4][8][68];
    __shared__ int   tka[4][8];
    int w = threadIdx.x >> 5;
    int lane = threadIdx.x & 31;
    int C = blockIdx.x * 4 + w;
    int bh = C >> 10;
    int Cl = C & 1023;
    int r = Cl >> 8, c = Cl & 255;
    int Cp = (Cl + 1023) & 1023;
    int rp = Cp >> 8, cp = Cp & 255;
    int b = bh >> 3, h = bh & 7;

    if (lane < 4) {
        tka[w][lane]     = g_st[(bh*NHASH + r)*NN + c*BSZ + lane];
        tka[w][lane + 4] = g_st[(bh*NHASH + rp)*NN + cp*BSZ + lane];
    }
    __syncwarp();

    ull v2[8];
    #pragma unroll
    for (int j = 0; j < 8; j++) {
        int t = tka[w][j];
        const float* ksrc = g_qk + ((size_t)(b*NN + t))*DD + h*DHD;
        const float* vsrc = g_v  + ((size_t)(b*NN + t))*DD + h*DHD;
        float2 kp = *(const float2*)(ksrc + 2*lane);
        float2 vp = *(const float2*)(vsrc + 2*lane);
        v2[j] = pack2(vp.x, vp.y);
        if (j < 4) *(float2*)&qs[w][j][2*lane] = kp;
        float ss = kp.x*kp.x + kp.y*kp.y;
        #pragma unroll
        for (int d = 16; d >= 1; d >>= 1) ss += __shfl_xor_sync(0xffffffffu, ss, d);
        float scale = 1.0f / fmaxf(sqrtf(ss), 1e-6f);
        float2 kn; kn.x = kp.x * scale; kn.y = kp.y * scale;
        *(float2*)&ks[w][j][2*lane] = kn;
    }
    __syncwarp();

    int i = lane >> 3, j = lane & 7;
    const ulonglong2* q2 = (const ulonglong2*)qs[w][i];
    const ulonglong2* k2 = (const ulonglong2*)ks[w][j];
    ull d2 = 0ull;
    #pragma unroll
    for (int fq = 0; fq < 16; fq++) {
        ulonglong2 a = q2[fq], kk = k2[fq];
        fma2(d2, a.x, kk.x);
        fma2(d2, a.y, kk.y);
    }
    float dlo, dhi;
    unpack2(d2, dlo, dhi);
    float d = (dlo + dhi) * 0.125f;
    if (tka[w][i] == tka[w][j]) d = -5e4f;

    float m = d;
    #pragma unroll
    for (int dd = 4; dd >= 1; dd >>= 1) m = fmaxf(m, __shfl_xor_sync(0xffffffffu, m, dd));
    float e = expf(d - m);
    float s = e;
    #pragma unroll
    for (int dd = 4; dd >= 1; dd >>= 1) s += __shfl_xor_sync(0xffffffffu, s, dd);
    float lse = m + logf(s);
    float pval = e / s;

    #pragma unroll
    for (int it = 0; it < 4; it++) {
        ull acc = 0ull;
        #pragma unroll
        for (int jj = 0; jj < 8; jj++) {
            float p = __shfl_sync(0xffffffffu, pval, it*8 + jj);
            fma2(acc, pack2(p, p), v2[jj]);
        }
        *(ull*)&g_o[(((size_t)(bh*NHASH + r))*NN + tka[w][it])*DHD + 2*lane] = acc;
    }
    if (j == 0)
        g_logits[(bh*NHASH + r)*NN + tka[w][i]] = lse;
}

// ---------------- K5: combine hash rounds + merge heads ---------------------
__global__ __launch_bounds__(256) void combine_kernel()
{
    int bh = blockIdx.y;
    int t = blockIdx.x * 8 + (threadIdx.x >> 5);
    int fp = threadIdx.x & 31;
    int b = bh >> 3, h = bh & 7;
    float l[NHASH];
    #pragma unroll
    for (int r = 0; r < NHASH; r++) l[r] = g_logits[(bh*NHASH + r)*NN + t];
    float m = fmaxf(fmaxf(l[0], l[1]), fmaxf(l[2], l[3]));
    float s = 0.f;
    #pragma unroll
    for (int r = 0; r < NHASH; r++) s += expf(l[r] - m);
    ull acc = 0ull;
    #pragma unroll
    for (int r = 0; r < NHASH; r++) {
        float wr = expf(l[r] - m) / s;
        ull wd = pack2(wr, wr);
        ull vv = *(const ull*)&g_o[(((size_t)(bh*NHASH + r))*NN + t)*DHD + fp*2];
        fma2(acc, wd, vv);
    }
    *(ull*)&g_att[((size_t)(b*NN + t))*DD + h*DHD + fp*2] = acc;
}

// ---------------- launch ----------------------------------------------------
extern "C" void kernel_launch(void* const* d_in, const int* in_sizes, int n_in,
                              void* d_out, int out_size)
{
    (void)in_sizes; (void)n_in; (void)out_size;
    const float* queries = (const float*)d_in[0];
    const float* Wqk  = (const float*)d_in[3];
    const float* Wv   = (const float*)d_in[4];
    const float* Wout = (const float*)d_in[5];
    const float* bout = (const float*)d_in[6];
    const float* rot  = (const float*)d_in[7];
    float* out = (float*)d_out;

    float *qk, *v, *att;
    unsigned *sh, *sl, *wvh, *wvl, *woh, *wol;
    cudaGetSymbolAddress((void**)&qk,  g_qk);
    cudaGetSymbolAddress((void**)&v,   g_v);
    cudaGetSymbolAddress((void**)&att, g_att);
    cudaGetSymbolAddress((void**)&sh,  g_sh);
    cudaGetSymbolAddress((void**)&sl,  g_sl);
    cudaGetSymbolAddress((void**)&wvh, g_wvh);
    cudaGetSymbolAddress((void**)&wvl, g_wvl);
    cudaGetSymbolAddress((void**)&woh, g_woh);
    cudaGetSymbolAddress((void**)&wol, g_wol);

    dim3 ggrid(DD/128, MTOT/128);   // (4, 64)
    // prep splits (weights + queries)
    split_w<<<DD*64/256, 256>>>(Wv,   wvh, wvl);
    split_w<<<DD*64/256, 256>>>(Wout, woh, wol);
    split_rows<<<MTOT*64/256, 256>>>(queries, sh, sl);
    // qk GEMM stays FFMA2 fp32 (bitwise-stable bucket decisions)
    sgemm128<false><<<ggrid, 256>>>(queries, Wqk, nullptr, qk, MTOT, DD, DD);
    hash_kernel<<<dim3(NN/64, BHN), 128>>>(rot);
    sort_kernel<<<BHN*NHASH, 256>>>();
    // v GEMM on tensor cores (3xTF32, pre-split, double-buffered)
    gemm_tc<false><<<ggrid, 256>>>(sh, sl, wvh, wvl, nullptr, v);
    attn_kernel<<<(BHN*CHTOT)/4, 128>>>();
    combine_kernel<<<dim3(NN/8, BHN), 256>>>();
    // split att (reuses sh/sl), then output GEMM + bias
    split_rows<<<MTOT*64/256, 256>>>(att, sh, sl);
    gemm_tc<true><<<ggrid, 256>>>(sh, sl, woh, wol, bout, out);
}

// round 13
// speedup vs baseline: 1.0628x; 1.0628x over previous
#include <cuda_runtime.h>
#include <math.h>

// ---------------- problem constants ----------------
#define BN     8
#define NN     1024
#define DD     512
#define HH     8
#define DHD    64
#define NHASH  4
#define NBUCK  256
#define BSZ    4
#define BHN    (BN*HH)
#define MTOT   (BN*NN)
#define CHTOT  (NHASH*NBUCK)

typedef unsigned long long ull;

// ---- packed f32x2 helpers (FFMA2; bit-exact fp32, 2 lanes/instr) -----------
__device__ __forceinline__ ull pack2(float lo, float hi) {
    ull r; asm("mov.b64 %0, {%1, %2};" : "=l"(r) : "f"(lo), "f"(hi)); return r;
}
__device__ __forceinline__ void unpack2(ull v, float& lo, float& hi) {
    asm("mov.b64 {%0, %1}, %2;" : "=f"(lo), "=f"(hi) : "l"(v));
}
__device__ __forceinline__ void fma2(ull& d, ull a, ull b) {
    asm("fma.rn.f32x2 %0, %1, %2, %0;" : "+l"(d) : "l"(a), "l"(b));
}

// ---- 3xTF32 helpers --------------------------------------------------------
__device__ __forceinline__ void tf32_split(float x, unsigned& hi, unsigned& lo) {
    unsigned h; asm("cvt.rna.tf32.f32 %0, %1;" : "=r"(h) : "f"(x));
    float r = x - __uint_as_float(h);
    unsigned l; asm("cvt.rna.tf32.f32 %0, %1;" : "=r"(l) : "f"(r));
    hi = h; lo = l;
}
__device__ __forceinline__ void mma_tf32(float* c, const unsigned* a, const unsigned* b) {
    asm volatile("mma.sync.aligned.m16n8k8.row.col.f32.tf32.tf32.f32 "
        "{%0,%1,%2,%3}, {%4,%5,%6,%7}, {%8,%9}, {%0,%1,%2,%3};"
        : "+f"(c[0]), "+f"(c[1]), "+f"(c[2]), "+f"(c[3])
        : "r"(a[0]), "r"(a[1]), "r"(a[2]), "r"(a[3]), "r"(b[0]), "r"(b[1]));
}

// ---------------- scratch ---------------------------------------------------
__device__ float    g_qk    [BN*NN*DD];
__device__ float    g_v     [BN*NN*DD];
__device__ int      g_bucket[BHN*NHASH*NN];
__device__ int      g_st    [BHN*NHASH*NN];
__device__ float    g_o     [(size_t)BHN*NHASH*NN*DHD];
__device__ float    g_logits[BHN*NHASH*NN];
__device__ float    g_att   [BN*NN*DD];
// pre-split tf32 operands, TILE-MAJOR layout for coalesced staging:
//   A: ((kt*MTOT + row)*8 + p),  B: ((kt*DD + n)*8 + p),  kt = k/8, p = perm pos
__device__ unsigned g_sh [MTOT*DD];
__device__ unsigned g_sl [MTOT*DD];
__device__ unsigned g_wvh[DD*DD];
__device__ unsigned g_wvl[DD*DD];
__device__ unsigned g_woh[DD*DD];
__device__ unsigned g_wol[DD*DD];

// perm within a k8 group: pos p holds k = (p>>1) + 4*(p&1)
// (so a uint2 at pos 2c,2c+1 = k-pair (c, c+4), matching the mma fragment)

// ---------------- prep: split rows [rows][512] -> tile-major hi/lo ----------
__global__ __launch_bounds__(256) void split_rows(
    const float* __restrict__ src, unsigned* __restrict__ hi, unsigned* __restrict__ lo)
{
    int id = blockIdx.x * 256 + threadIdx.x;      // MTOT*64 threads
    int kg = id >> 13, row = id & (MTOT - 1);     // MTOT = 8192 = 2^13
    const float* s = src + (size_t)row * DD + kg * 8;
    float4 v0 = *(const float4*)s;
    float4 v1 = *(const float4*)(s + 4);
    float f[8] = {v0.x, v0.y, v0.z, v0.w, v1.x, v1.y, v1.z, v1.w};
    unsigned oh[8], ol[8];
    #pragma unroll
    for (int p = 0; p < 8; p++) {
        int k = (p >> 1) + 4 * (p & 1);
        tf32_split(f[k], oh[p], ol[p]);
    }
    size_t off = ((size_t)kg * MTOT + row) * 8;   // tile-major, coalesced write
    *(uint4*)(hi + off)     = make_uint4(oh[0], oh[1], oh[2], oh[3]);
    *(uint4*)(hi + off + 4) = make_uint4(oh[4], oh[5], oh[6], oh[7]);
    *(uint4*)(lo + off)     = make_uint4(ol[0], ol[1], ol[2], ol[3]);
    *(uint4*)(lo + off + 4) = make_uint4(ol[4], ol[5], ol[6], ol[7]);
}

// ---------------- prep: split W[k][n] -> tile-major [kt][n][perm8] hi/lo ----
__global__ __launch_bounds__(256) void split_w(
    const float* __restrict__ w, unsigned* __restrict__ hi, unsigned* __restrict__ lo)
{
    int id = blockIdx.x * 256 + threadIdx.x;      // 64*512 threads
    int kg = id >> 9, n = id & 511;
    float f[8];
    #pragma unroll
    for (int kw = 0; kw < 8; kw++)
        f[kw] = w[(size_t)(kg * 8 + kw) * DD + n];
    unsigned oh[8], ol[8];
    #pragma unroll
    for (int p = 0; p < 8; p++) {
        int k = (p >> 1) + 4 * (p & 1);
        tf32_split(f[k], oh[p], ol[p]);
    }
    size_t off = ((size_t)kg * DD + n) * 8;       // tile-major, coalesced write
    *(uint4*)(hi + off)     = make_uint4(oh[0], oh[1], oh[2], oh[3]);
    *(uint4*)(hi + off + 4) = make_uint4(oh[4], oh[5], oh[6], oh[7]);
    *(uint4*)(lo + off)     = make_uint4(ol[0], ol[1], ol[2], ol[3]);
    *(uint4*)(lo + off + 4) = make_uint4(ol[4], ol[5], ol[6], ol[7]);
}

// ---------------- K1 (qk): SGEMM 128x128, BK=8, FFMA2 (proven R6 version) ---
template<bool HASBIAS>
__global__ __launch_bounds__(256, 2) void sgemm128(
    const float* __restrict__ A, const float* __restrict__ Bm,
    const float* __restrict__ bias, float* __restrict__ C,
    int M, int Nn, int K)
{
    __shared__ __align__(16) float As[2][8][132];
    __shared__ __align__(16) float Bs[2][8][132];
    int tid = threadIdx.x;
    int bm = blockIdx.y * 128, bn = blockIdx.x * 128;
    int ty = tid >> 4, tx = tid & 15;

    int arow = tid >> 1;
    int akq  = (tid & 1) * 4;
    int bk   = tid >> 5;
    int bnq  = (tid & 31) * 4;

    const float* Aptr = A  + (size_t)(bm + arow) * K + akq;
    const float* Bptr = Bm + (size_t)bk * Nn + bn + bnq;

    ull acc[8][4];
    #pragma unroll
    for (int i = 0; i < 8; i++)
        #pragma unroll
        for (int jp = 0; jp < 4; jp++) acc[i][jp] = 0ull;

    float4 av = *(const float4*)(Aptr);
    float4 bv = *(const float4*)(Bptr);
    As[0][akq+0][arow] = av.x;
    As[0][akq+1][arow] = av.y;
    As[0][akq+2][arow] = av.z;
    As[0][akq+3][arow] = av.w;
    *(float4*)&Bs[0][bk][bnq] = bv;
    __syncthreads();

    int buf = 0;
    for (int k0 = 8; k0 <= K; k0 += 8) {
        if (k0 < K) {
            av = *(const float4*)(Aptr + k0);
            bv = *(const float4*)(Bptr + (size_t)k0 * Nn);
        }
        #pragma unroll
        for (int k = 0; k < 8; k++) {
            float4 a0 = *(const float4*)&As[buf][k][ty*4];
            float4 a1 = *(const float4*)&As[buf][k][64 + ty*4];
            ulonglong2 b0 = *(const ulonglong2*)&Bs[buf][k][tx*4];
            ulonglong2 b1 = *(const ulonglong2*)&Bs[buf][k][64 + tx*4];
            ull ad[8];
            ad[0] = pack2(a0.x, a0.x); ad[1] = pack2(a0.y, a0.y);
            ad[2] = pack2(a0.z, a0.z); ad[3] = pack2(a0.w, a0.w);
            ad[4] = pack2(a1.x, a1.x); ad[5] = pack2(a1.y, a1.y);
            ad[6] = pack2(a1.z, a1.z); ad[7] = pack2(a1.w, a1.w);
            #pragma unroll
            for (int i = 0; i < 8; i++) {
                fma2(acc[i][0], ad[i], b0.x);
                fma2(acc[i][1], ad[i], b0.y);
                fma2(acc[i][2], ad[i], b1.x);
                fma2(acc[i][3], ad[i], b1.y);
            }
        }
        if (k0 < K) {
            buf ^= 1;
            As[buf][akq+0][arow] = av.x;
            As[buf][akq+1][arow] = av.y;
            As[buf][akq+2][arow] = av.z;
            As[buf][akq+3][arow] = av.w;
            *(float4*)&Bs[buf][bk][bnq] = bv;
            __syncthreads();
        }
    }

    #pragma unroll
    for (int rh = 0; rh < 2; rh++)
        #pragma unroll
        for (int i = 0; i < 4; i++) {
            int row = bm + rh*64 + ty*4 + i;
            #pragma unroll
            for (int ch = 0; ch < 2; ch++) {
                float4 o;
                unpack2(acc[rh*4+i][ch*2+0], o.x, o.y);
                unpack2(acc[rh*4+i][ch*2+1], o.z, o.w);
                int col = bn + ch*64 + tx*4;
                if (HASBIAS) {
                    o.x += bias[col+0]; o.y += bias[col+1];
                    o.z += bias[col+2]; o.w += bias[col+3];
                }
                *(float4*)(C + (size_t)row * Nn + col) = o;
            }
        }
}

// ---------------- K1b (v, out): 3xTF32 TC GEMM, tile-major, double-buffered -
// Block 128x128, 256 thr (8 warps 2x4), warp tile 64x32, BK=8, K=512 fixed.
// Staging LDG now fully coalesced (warp reads 512B contiguous per LDG.128).
template<bool HASBIAS>
__global__ __launch_bounds__(256, 2) void gemm_tc(
    const unsigned* __restrict__ Ahg, const unsigned* __restrict__ Alg,
    const unsigned* __restrict__ Bhg, const unsigned* __restrict__ Blg,
    const float* __restrict__ bias, float* __restrict__ C)
{
    __shared__ unsigned sAh[2][128][8], sAl[2][128][8];
    __shared__ unsigned sBh[2][128][8], sBl[2][128][8];
    int tid = threadIdx.x;
    int bm = blockIdx.y * 128, bn = blockIdx.x * 128;
    int wid = tid >> 5, lane = tid & 31;
    int m0 = (wid >> 2) * 64, n0 = (wid & 3) * 32;
    int grp = lane >> 2, cc = lane & 3;

    // staging map: thread owns half a row (uint4); tile-major -> coalesced
    int sr = tid >> 1, pp = (tid & 1) * 4;
    const unsigned* pAh = Ahg + ((size_t)(bm + sr)) * 8 + pp;
    const unsigned* pAl = Alg + ((size_t)(bm + sr)) * 8 + pp;
    const unsigned* pBh = Bhg + ((size_t)(bn + sr)) * 8 + pp;
    const unsigned* pBl = Blg + ((size_t)(bn + sr)) * 8 + pp;

    float acc[4][4][4];
    #pragma unroll
    for (int t = 0; t < 4; t++)
        #pragma unroll
        for (int u = 0; u < 4; u++)
            #pragma unroll
            for (int x = 0; x < 4; x++) acc[t][u][x] = 0.f;

    // prologue: tile 0
    uint4 vah = *(const uint4*)(pAh);
    uint4 val = *(const uint4*)(pAl);
    uint4 vbh = *(const uint4*)(pBh);
    uint4 vbl = *(const uint4*)(pBl);
    *(uint4*)&sAh[0][sr][pp] = vah;
    *(uint4*)&sAl[0][sr][pp] = val;
    *(uint4*)&sBh[0][sr][pp] = vbh;
    *(uint4*)&sBl[0][sr][pp] = vbl;
    __syncthreads();

    int buf = 0;
    for (int kt = 1; kt <= 64; kt++) {
        if (kt < 64) {
            vah = *(const uint4*)(pAh + (size_t)kt * MTOT * 8);
            val = *(const uint4*)(pAl + (size_t)kt * MTOT * 8);
            vbh = *(const uint4*)(pBh + (size_t)kt * DD * 8);
            vbl = *(const uint4*)(pBl + (size_t)kt * DD * 8);
        }
        // B fragments for all u
        uint2 bfh[4], bfl[4];
        #pragma unroll
        for (int u = 0; u < 4; u++) {
            int nr = n0 + u*8 + grp;
            bfh[u] = *(const uint2*)&sBh[buf][nr][2*cc];
            bfl[u] = *(const uint2*)&sBl[buf][nr][2*cc];
        }
        #pragma unroll
        for (int t = 0; t < 4; t++) {
            int r0 = m0 + t*16 + grp;
            uint2 h0 = *(const uint2*)&sAh[buf][r0  ][2*cc];
            uint2 h1 = *(const uint2*)&sAh[buf][r0+8][2*cc];
            uint2 l0 = *(const uint2*)&sAl[buf][r0  ][2*cc];
            uint2 l1 = *(const uint2*)&sAl[buf][r0+8][2*cc];
            unsigned afh[4] = {h0.x, h1.x, h0.y, h1.y};
            unsigned afl[4] = {l0.x, l1.x, l0.y, l1.y};
            #pragma unroll
            for (int u = 0; u < 4; u++) {
                unsigned bh2[2] = {bfh[u].x, bfh[u].y};
                unsigned bl2[2] = {bfl[u].x, bfl[u].y};
                mma_tf32(acc[t][u], afl, bh2);   // Al*Bb
                mma_tf32(acc[t][u], afh, bl2);   // Ab*Bl
                mma_tf32(acc[t][u], afh, bh2);   // Ab*Bb
            }
        }
        if (kt < 64) {
            buf ^= 1;
            *(uint4*)&sAh[buf][sr][pp] = vah;
            *(uint4*)&sAl[buf][sr][pp] = val;
            *(uint4*)&sBh[buf][sr][pp] = vbh;
            *(uint4*)&sBl[buf][sr][pp] = vbl;
            __syncthreads();
        }
    }

    #pragma unroll
    for (int t = 0; t < 4; t++)
        #pragma unroll
        for (int u = 0; u < 4; u++) {
            int row = bm + m0 + t*16 + grp;
            int col = bn + n0 + u*8 + 2*cc;
            float2 o0 = make_float2(acc[t][u][0], acc[t][u][1]);
            float2 o1 = make_float2(acc[t][u][2], acc[t][u][3]);
            if (HASBIAS) {
                float2 bv = *(const float2*)(bias + col);
                o0.x += bv.x; o0.y += bv.y; o1.x += bv.x; o1.y += bv.y;
            }
            *(float2*)(C + (size_t)row * DD + col)       = o0;
            *(float2*)(C + (size_t)(row + 8) * DD + col) = o1;
        }
}

// ---------------- K2: LSH hashing, FFMA2 (bitwise-stable buckets) -----------
__global__ __launch_bounds__(128) void hash_kernel(const float* __restrict__ rot)
{
    __shared__ __align__(16) float qs[64][64];
    __shared__ __align__(16) float rs[64][128];
    int bh = blockIdx.y;
    int t0 = blockIdx.x * 64;
    int b = bh >> 3, h = bh & 7;
    int tid = threadIdx.x;
    int quad = tid >> 3, ig = tid & 7;

    for (int idx = tid; idx < 64*16; idx += 128) {
        int tk = idx >> 4, fq = (idx & 15) * 4;
        *(float4*)&qs[tk][fq] =
            *(const float4*)(g_qk + ((size_t)(b*NN + t0 + tk))*DD + h*DHD + fq);
    }

    for (int r = 0; r < NHASH; r++) {
        __syncthreads();
        for (int idx = tid; idx < 64*32; idx += 128) {
            int f = idx >> 5, iq = (idx & 31) * 4;
            *(float4*)&rs[f][iq] = *(const float4*)(rot + f*(NHASH*128) + r*128 + iq);
        }
        __syncthreads();

        ull acc2[4][4][2];
        #pragma unroll
        for (int tt = 0; tt < 4; tt++)
            #pragma unroll
            for (int c = 0; c < 4; c++) {
                acc2[tt][c][0] = 0ull; acc2[tt][c][1] = 0ull;
            }

        for (int f = 0; f < 64; f++) {
            ull qd[4];
            #pragma unroll
            for (int tt = 0; tt < 4; tt++) {
                float q = qs[quad*4 + tt][f];
                qd[tt] = pack2(q, q);
            }
            #pragma unroll
            for (int c = 0; c < 4; c++) {
                ulonglong2 rv = *(const ulonglong2*)&rs[f][ig*4 + c*32];
                #pragma unroll
                for (int tt = 0; tt < 4; tt++) {
                    fma2(acc2[tt][c][0], qd[tt], rv.x);
                    fma2(acc2[tt][c][1], qd[tt], rv.y);
                }
            }
        }

        #pragma unroll
        for (int tt = 0; tt < 4; tt++) {
            float bvv = -1e30f; int bi = 256;
            #pragma unroll
            for (int c = 0; c < 4; c++)
                #pragma unroll
                for (int jp = 0; jp < 2; jp++) {
                    float v0, v1;
                    unpack2(acc2[tt][c][jp], v0, v1);
                    float vv[2] = {v0, v1};
                    #pragma unroll
                    for (int u = 0; u < 2; u++) {
                        int i = ig*4 + c*32 + jp*2 + u;
                        float v = vv[u];
                        if (v > bvv || (v == bvv && i < bi)) { bvv = v; bi = i; }
                        float vn = -v; int i2 = 128 + i;
                        if (vn > bvv || (vn == bvv && i2 < bi)) { bvv = vn; bi = i2; }
                    }
                }
            #pragma unroll
            for (int m = 1; m < 8; m <<= 1) {
                float ov = __shfl_xor_sync(0xffffffffu, bvv, m);
                int   oi = __shfl_xor_sync(0xffffffffu, bi, m);
                if (ov > bvv || (ov == bvv && oi < bi)) { bvv = ov; bi = oi; }
            }
            if (ig == 0)
                g_bucket[(bh*NHASH + r)*NN + t0 + quad*4 + tt] = bi;
        }
    }
}

// ---------------- K3: stable counting sort per (bh, round) ------------------
__global__ __launch_bounds__(256) void sort_kernel()
{
    __shared__ __align__(16) int bks[NN];
    __shared__ int tmp[NN];
    __shared__ int hist[NBUCK];
    __shared__ int offs[NBUCK];
    __shared__ int cnt[NBUCK];
    __shared__ int wsum[8];
    int bhr = blockIdx.x;
    int tid = threadIdx.x;
    for (int t = tid; t < NN; t += 256) bks[t] = g_bucket[bhr*NN + t];
    hist[tid] = 0; cnt[tid] = 0;
    __syncthreads();
    for (int t = tid; t < NN; t += 256) atomicAdd(&hist[bks[t]], 1);
    __syncthreads();
    int hv = hist[tid];
    int incl = hv;
    #pragma unroll
    for (int d = 1; d < 32; d <<= 1) {
        int nv = __shfl_up_sync(0xffffffffu, incl, d);
        if ((tid & 31) >= d) incl += nv;
    }
    if ((tid & 31) == 31) wsum[tid >> 5] = incl;
    __syncthreads();
    if (tid == 0) {
        int s = 0;
        #pragma unroll
        for (int k = 0; k < 8; k++) { int t = wsum[k]; wsum[k] = s; s += t; }
    }
    __syncthreads();
    offs[tid] = incl - hv + wsum[tid >> 5];
    __syncthreads();
    for (int t = tid; t < NN; t += 256) {
        int b = bks[t];
        int p = atomicAdd(&cnt[b], 1);
        tmp[offs[b] + p] = t;
    }
    __syncthreads();
    {
        int o = offs[tid], k = hist[tid];
        for (int x = 1; x < k; x++) {
            int key = tmp[o + x];
            int y = x - 1;
            while (y >= 0 && tmp[o + y] > key) { tmp[o + y + 1] = tmp[o + y]; y--; }
            tmp[o + y + 1] = key;
        }
    }
    __syncthreads();
    for (int t = tid; t < NN; t += 256) g_st[bhr*NN + t] = tmp[t];
}

// ---------------- K4: chunked attention, lane-pair layout -------------------
__global__ __launch_bounds__(128) void attn_kernel()
{
    __shared__ __align__(16) float qs[4][4][68];
    __shared__ __align__(16) float ks[4][8][68];
    __shared__ int   tka[4][8];
    int w = threadIdx.x >> 5;
    int lane = threadIdx.x & 31;
    int C = blockIdx.x * 4 + w;
    int bh = C >> 10;
    int Cl = C & 1023;
    int r = Cl >> 8, c = Cl & 255;
    int Cp = (Cl + 1023) & 1023;
    int rp = Cp >> 8, cp = Cp & 255;
    int b = bh >> 3, h = bh & 7;

    if (lane < 4) {
        tka[w][lane]     = g_st[(bh*NHASH + r)*NN + c*BSZ + lane];
        tka[w][lane + 4] = g_st[(bh*NHASH + rp)*NN + cp*BSZ + lane];
    }
    __syncwarp();

    ull v2[8];
    #pragma unroll
    for (int j = 0; j < 8; j++) {
        int t = tka[w][j];
        const float* ksrc = g_qk + ((size_t)(b*NN + t))*DD + h*DHD;
        const float* vsrc = g_v  + ((size_t)(b*NN + t))*DD + h*DHD;
        float2 kp = *(const float2*)(ksrc + 2*lane);
        float2 vp = *(const float2*)(vsrc + 2*lane);
        v2[j] = pack2(vp.x, vp.y);
        if (j < 4) *(float2*)&qs[w][j][2*lane] = kp;
        float ss = kp.x*kp.x + kp.y*kp.y;
        #pragma unroll
        for (int d = 16; d >= 1; d >>= 1) ss += __shfl_xor_sync(0xffffffffu, ss, d);
        float scale = 1.0f / fmaxf(sqrtf(ss), 1e-6f);
        float2 kn; kn.x = kp.x * scale; kn.y = kp.y * scale;
        *(float2*)&ks[w][j][2*lane] = kn;
    }
    __syncwarp();

    int i = lane >> 3, j = lane & 7;
    const ulonglong2* q2 = (const ulonglong2*)qs[w][i];
    const ulonglong2* k2 = (const ulonglong2*)ks[w][j];
    ull d2 = 0ull;
    #pragma unroll
    for (int fq = 0; fq < 16; fq++) {
        ulonglong2 a = q2[fq], kk = k2[fq];
        fma2(d2, a.x, kk.x);
        fma2(d2, a.y, kk.y);
    }
    float dlo, dhi;
    unpack2(d2, dlo, dhi);
    float d = (dlo + dhi) * 0.125f;
    if (tka[w][i] == tka[w][j]) d = -5e4f;

    float m = d;
    #pragma unroll
    for (int dd = 4; dd >= 1; dd >>= 1) m = fmaxf(m, __shfl_xor_sync(0xffffffffu, m, dd));
    float e = expf(d - m);
    float s = e;
    #pragma unroll
    for (int dd = 4; dd >= 1; dd >>= 1) s += __shfl_xor_sync(0xffffffffu, s, dd);
    float lse = m + logf(s);
    float pval = e / s;

    #pragma unroll
    for (int it = 0; it < 4; it++) {
        ull acc = 0ull;
        #pragma unroll
        for (int jj = 0; jj < 8; jj++) {
            float p = __shfl_sync(0xffffffffu, pval, it*8 + jj);
            fma2(acc, pack2(p, p), v2[jj]);
        }
        *(ull*)&g_o[(((size_t)(bh*NHASH + r))*NN + tka[w][it])*DHD + 2*lane] = acc;
    }
    if (j == 0)
        g_logits[(bh*NHASH + r)*NN + tka[w][i]] = lse;
}

// ---------------- K5: combine hash rounds + merge heads ---------------------
__global__ __launch_bounds__(256) void combine_kernel()
{
    int bh = blockIdx.y;
    int t = blockIdx.x * 8 + (threadIdx.x >> 5);
    int fp = threadIdx.x & 31;
    int b = bh >> 3, h = bh & 7;
    float l[NHASH];
    #pragma unroll
    for (int r = 0; r < NHASH; r++) l[r] = g_logits[(bh*NHASH + r)*NN + t];
    float m = fmaxf(fmaxf(l[0], l[1]), fmaxf(l[2], l[3]));
    float s = 0.f;
    #pragma unroll
    for (int r = 0; r < NHASH; r++) s += expf(l[r] - m);
    ull acc = 0ull;
    #pragma unroll
    for (int r = 0; r < NHASH; r++) {
        float wr = expf(l[r] - m) / s;
        ull wd = pack2(wr, wr);
        ull vv = *(const ull*)&g_o[(((size_t)(bh*NHASH + r))*NN + t)*DHD + fp*2];
        fma2(acc, wd, vv);
    }
    *(ull*)&g_att[((size_t)(b*NN + t))*DD + h*DHD + fp*2] = acc;
}

// ---------------- launch ----------------------------------------------------
extern "C" void kernel_launch(void* const* d_in, const int* in_sizes, int n_in,
                              void* d_out, int out_size)
{
    (void)in_sizes; (void)n_in; (void)out_size;
    const float* queries = (const float*)d_in[0];
    const float* Wqk  = (const float*)d_in[3];
    const float* Wv   = (const float*)d_in[4];
    const float* Wout = (const float*)d_in[5];
    const float* bout = (const float*)d_in[6];
    const float* rot  = (const float*)d_in[7];
    float* out = (float*)d_out;

    float *qk, *v, *att;
    unsigned *sh, *sl, *wvh, *wvl, *woh, *wol;
    cudaGetSymbolAddress((void**)&qk,  g_qk);
    cudaGetSymbolAddress((void**)&v,   g_v);
    cudaGetSymbolAddress((void**)&att, g_att);
    cudaGetSymbolAddress((void**)&sh,  g_sh);
    cudaGetSymbolAddress((void**)&sl,  g_sl);
    cudaGetSymbolAddress((void**)&wvh, g_wvh);
    cudaGetSymbolAddress((void**)&wvl, g_wvl);
    cudaGetSymbolAddress((void**)&woh, g_woh);
    cudaGetSymbolAddress((void**)&wol, g_wol);

    dim3 ggrid(DD/128, MTOT/128);   // (4, 64)
    // prep splits (weights + queries)
    split_w<<<DD*64/256, 256>>>(Wv,   wvh, wvl);
    split_w<<<DD*64/256, 256>>>(Wout, woh, wol);
    split_rows<<<MTOT*64/256, 256>>>(queries, sh, sl);
    // qk GEMM stays FFMA2 fp32 (bitwise-stable bucket decisions)
    sgemm128<false><<<ggrid, 256>>>(queries, Wqk, nullptr, qk, MTOT, DD, DD);
    hash_kernel<<<dim3(NN/64, BHN), 128>>>(rot);
    sort_kernel<<<BHN*NHASH, 256>>>();
    // v GEMM on tensor cores (3xTF32, tile-major pre-split, double-buffered)
    gemm_tc<false><<<ggrid, 256>>>(sh, sl, wvh, wvl, nullptr, v);
    attn_kernel<<<(BHN*CHTOT)/4, 128>>>();
    combine_kernel<<<dim3(NN/8, BHN), 256>>>();
    // split att (reuses sh/sl), then output GEMM + bias
    split_rows<<<MTOT*64/256, 256>>>(att, sh, sl);
    gemm_tc<true><<<ggrid, 256>>>(sh, sl, woh, wol, bout, out);
}

// round 15
// speedup vs baseline: 1.0772x; 1.0135x over previous
#include <cuda_runtime.h>
#include <math.h>

// ---------------- problem constants ----------------
#define BN     8
#define NN     1024
#define DD     512
#define HH     8
#define DHD    64
#define NHASH  4
#define NBUCK  256
#define BSZ    4
#define BHN    (BN*HH)
#define MTOT   (BN*NN)
#define CHTOT  (NHASH*NBUCK)

typedef unsigned long long ull;

// ---- packed f32x2 helpers (FFMA2; bit-exact fp32, 2 lanes/instr) -----------
__device__ __forceinline__ ull pack2(float lo, float hi) {
    ull r; asm("mov.b64 %0, {%1, %2};" : "=l"(r) : "f"(lo), "f"(hi)); return r;
}
__device__ __forceinline__ void unpack2(ull v, float& lo, float& hi) {
    asm("mov.b64 {%0, %1}, %2;" : "=f"(lo), "=f"(hi) : "l"(v));
}
__device__ __forceinline__ void fma2(ull& d, ull a, ull b) {
    asm("fma.rn.f32x2 %0, %1, %2, %0;" : "+l"(d) : "l"(a), "l"(b));
}

// ---- 3xTF32 helpers --------------------------------------------------------
__device__ __forceinline__ void tf32_split(float x, unsigned& hi, unsigned& lo) {
    unsigned h; asm("cvt.rna.tf32.f32 %0, %1;" : "=r"(h) : "f"(x));
    float r = x - __uint_as_float(h);
    unsigned l; asm("cvt.rna.tf32.f32 %0, %1;" : "=r"(l) : "f"(r));
    hi = h; lo = l;
}
__device__ __forceinline__ void mma_tf32(float* c, const unsigned* a, const unsigned* b) {
    asm volatile("mma.sync.aligned.m16n8k8.row.col.f32.tf32.tf32.f32 "
        "{%0,%1,%2,%3}, {%4,%5,%6,%7}, {%8,%9}, {%0,%1,%2,%3};"
        : "+f"(c[0]), "+f"(c[1]), "+f"(c[2]), "+f"(c[3])
        : "r"(a[0]), "r"(a[1]), "r"(a[2]), "r"(a[3]), "r"(b[0]), "r"(b[1]));
}

// ---------------- scratch ---------------------------------------------------
__device__ float    g_qk    [BN*NN*DD];
__device__ float    g_v     [BN*NN*DD];
__device__ int      g_bucket[BHN*NHASH*NN];
__device__ int      g_st    [BHN*NHASH*NN];
__device__ float    g_o     [(size_t)BHN*NHASH*NN*DHD];
__device__ float    g_logits[BHN*NHASH*NN];
// pre-split tf32 operands, TILE-MAJOR layout:
//   A: ((kt*MTOT + row)*8 + p),  B: ((kt*DD + n)*8 + p),  kt = k/8, p = perm pos
__device__ unsigned g_sh [MTOT*DD];
__device__ unsigned g_sl [MTOT*DD];
__device__ unsigned g_wvh[DD*DD];
__device__ unsigned g_wvl[DD*DD];
__device__ unsigned g_woh[DD*DD];
__device__ unsigned g_wol[DD*DD];

// perm within a k8 group: pos p holds k = (p>>1) + 4*(p&1); inverse p(k) = 2*(k&3)+(k>>2)

// ---------------- prep: split rows [rows][512] -> tile-major hi/lo ----------
__global__ __launch_bounds__(256) void split_rows(
    const float* __restrict__ src, unsigned* __restrict__ hi, unsigned* __restrict__ lo)
{
    int id = blockIdx.x * 256 + threadIdx.x;      // MTOT*64 threads
    int kg = id >> 13, row = id & (MTOT - 1);     // MTOT = 8192 = 2^13
    const float* s = src + (size_t)row * DD + kg * 8;
    float4 v0 = *(const float4*)s;
    float4 v1 = *(const float4*)(s + 4);
    float f[8] = {v0.x, v0.y, v0.z, v0.w, v1.x, v1.y, v1.z, v1.w};
    unsigned oh[8], ol[8];
    #pragma unroll
    for (int p = 0; p < 8; p++) {
        int k = (p >> 1) + 4 * (p & 1);
        tf32_split(f[k], oh[p], ol[p]);
    }
    size_t off = ((size_t)kg * MTOT + row) * 8;
    *(uint4*)(hi + off)     = make_uint4(oh[0], oh[1], oh[2], oh[3]);
    *(uint4*)(hi + off + 4) = make_uint4(oh[4], oh[5], oh[6], oh[7]);
    *(uint4*)(lo + off)     = make_uint4(ol[0], ol[1], ol[2], ol[3]);
    *(uint4*)(lo + off + 4) = make_uint4(ol[4], ol[5], ol[6], ol[7]);
}

// ---------------- prep: split W[k][n] -> tile-major [kt][n][perm8] hi/lo ----
__global__ __launch_bounds__(256) void split_w(
    const float* __restrict__ w, unsigned* __restrict__ hi, unsigned* __restrict__ lo)
{
    int id = blockIdx.x * 256 + threadIdx.x;      // 64*512 threads
    int kg = id >> 9, n = id & 511;
    float f[8];
    #pragma unroll
    for (int kw = 0; kw < 8; kw++)
        f[kw] = w[(size_t)(kg * 8 + kw) * DD + n];
    unsigned oh[8], ol[8];
    #pragma unroll
    for (int p = 0; p < 8; p++) {
        int k = (p >> 1) + 4 * (p & 1);
        tf32_split(f[k], oh[p], ol[p]);
    }
    size_t off = ((size_t)kg * DD + n) * 8;
    *(uint4*)(hi + off)     = make_uint4(oh[0], oh[1], oh[2], oh[3]);
    *(uint4*)(hi + off + 4) = make_uint4(oh[4], oh[5], oh[6], oh[7]);
    *(uint4*)(lo + off)     = make_uint4(ol[0], ol[1], ol[2], ol[3]);
    *(uint4*)(lo + off + 4) = make_uint4(ol[4], ol[5], ol[6], ol[7]);
}

// ---------------- K1 (qk): SGEMM 128x128, BK=8, FFMA2 (proven; EXACT fp32) --
template<bool HASBIAS>
__global__ __launch_bounds__(256, 2) void sgemm128(
    const float* __restrict__ A, const float* __restrict__ Bm,
    const float* __restrict__ bias, float* __restrict__ C,
    int M, int Nn, int K)
{
    __shared__ __align__(16) float As[2][8][132];
    __shared__ __align__(16) float Bs[2][8][132];
    int tid = threadIdx.x;
    int bm = blockIdx.y * 128, bn = blockIdx.x * 128;
    int ty = tid >> 4, tx = tid & 15;

    int arow = tid >> 1;
    int akq  = (tid & 1) * 4;
    int bk   = tid >> 5;
    int bnq  = (tid & 31) * 4;

    const float* Aptr = A  + (size_t)(bm + arow) * K + akq;
    const float* Bptr = Bm + (size_t)bk * Nn + bn + bnq;

    ull acc[8][4];
    #pragma unroll
    for (int i = 0; i < 8; i++)
        #pragma unroll
        for (int jp = 0; jp < 4; jp++) acc[i][jp] = 0ull;

    float4 av = *(const float4*)(Aptr);
    float4 bv = *(const float4*)(Bptr);
    As[0][akq+0][arow] = av.x;
    As[0][akq+1][arow] = av.y;
    As[0][akq+2][arow] = av.z;
    As[0][akq+3][arow] = av.w;
    *(float4*)&Bs[0][bk][bnq] = bv;
    __syncthreads();

    int buf = 0;
    for (int k0 = 8; k0 <= K; k0 += 8) {
        if (k0 < K) {
            av = *(const float4*)(Aptr + k0);
            bv = *(const float4*)(Bptr + (size_t)k0 * Nn);
        }
        #pragma unroll
        for (int k = 0; k < 8; k++) {
            float4 a0 = *(const float4*)&As[buf][k][ty*4];
            float4 a1 = *(const float4*)&As[buf][k][64 + ty*4];
            ulonglong2 b0 = *(const ulonglong2*)&Bs[buf][k][tx*4];
            ulonglong2 b1 = *(const ulonglong2*)&Bs[buf][k][64 + tx*4];
            ull ad[8];
            ad[0] = pack2(a0.x, a0.x); ad[1] = pack2(a0.y, a0.y);
            ad[2] = pack2(a0.z, a0.z); ad[3] = pack2(a0.w, a0.w);
            ad[4] = pack2(a1.x, a1.x); ad[5] = pack2(a1.y, a1.y);
            ad[6] = pack2(a1.z, a1.z); ad[7] = pack2(a1.w, a1.w);
            #pragma unroll
            for (int i = 0; i < 8; i++) {
                fma2(acc[i][0], ad[i], b0.x);
                fma2(acc[i][1], ad[i], b0.y);
                fma2(acc[i][2], ad[i], b1.x);
                fma2(acc[i][3], ad[i], b1.y);
            }
        }
        if (k0 < K) {
            buf ^= 1;
            As[buf][akq+0][arow] = av.x;
            As[buf][akq+1][arow] = av.y;
            As[buf][akq+2][arow] = av.z;
            As[buf][akq+3][arow] = av.w;
            *(float4*)&Bs[buf][bk][bnq] = bv;
            __syncthreads();
        }
    }

    #pragma unroll
    for (int rh = 0; rh < 2; rh++)
        #pragma unroll
        for (int i = 0; i < 4; i++) {
            int row = bm + rh*64 + ty*4 + i;
            #pragma unroll
            for (int ch = 0; ch < 2; ch++) {
                float4 o;
                unpack2(acc[rh*4+i][ch*2+0], o.x, o.y);
                unpack2(acc[rh*4+i][ch*2+1], o.z, o.w);
                int col = bn + ch*64 + tx*4;
                if (HASBIAS) {
                    o.x += bias[col+0]; o.y += bias[col+1];
                    o.z += bias[col+2]; o.w += bias[col+3];
                }
                *(float4*)(C + (size_t)row * Nn + col) = o;
            }
        }
}

// ---------------- K1b (v, out): 3xTF32 TC GEMM, tile-major, double-buffered -
template<bool HASBIAS>
__global__ __launch_bounds__(256, 2) void gemm_tc(
    const unsigned* __restrict__ Ahg, const unsigned* __restrict__ Alg,
    const unsigned* __restrict__ Bhg, const unsigned* __restrict__ Blg,
    const float* __restrict__ bias, float* __restrict__ C)
{
    __shared__ unsigned sAh[2][128][8], sAl[2][128][8];
    __shared__ unsigned sBh[2][128][8], sBl[2][128][8];
    int tid = threadIdx.x;
    int bm = blockIdx.y * 128, bn = blockIdx.x * 128;
    int wid = tid >> 5, lane = tid & 31;
    int m0 = (wid >> 2) * 64, n0 = (wid & 3) * 32;
    int grp = lane >> 2, cc = lane & 3;

    int sr = tid >> 1, pp = (tid & 1) * 4;
    const unsigned* pAh = Ahg + ((size_t)(bm + sr)) * 8 + pp;
    const unsigned* pAl = Alg + ((size_t)(bm + sr)) * 8 + pp;
    const unsigned* pBh = Bhg + ((size_t)(bn + sr)) * 8 + pp;
    const unsigned* pBl = Blg + ((size_t)(bn + sr)) * 8 + pp;

    float acc[4][4][4];
    #pragma unroll
    for (int t = 0; t < 4; t++)
        #pragma unroll
        for (int u = 0; u < 4; u++)
            #pragma unroll
            for (int x = 0; x < 4; x++) acc[t][u][x] = 0.f;

    uint4 vah = *(const uint4*)(pAh);
    uint4 val = *(const uint4*)(pAl);
    uint4 vbh = *(const uint4*)(pBh);
    uint4 vbl = *(const uint4*)(pBl);
    *(uint4*)&sAh[0][sr][pp] = vah;
    *(uint4*)&sAl[0][sr][pp] = val;
    *(uint4*)&sBh[0][sr][pp] = vbh;
    *(uint4*)&sBl[0][sr][pp] = vbl;
    __syncthreads();

    int buf = 0;
    for (int kt = 1; kt <= 64; kt++) {
        if (kt < 64) {
            vah = *(const uint4*)(pAh + (size_t)kt * MTOT * 8);
            val = *(const uint4*)(pAl + (size_t)kt * MTOT * 8);
            vbh = *(const uint4*)(pBh + (size_t)kt * DD * 8);
            vbl = *(const uint4*)(pBl + (size_t)kt * DD * 8);
        }
        uint2 bfh[4], bfl[4];
        #pragma unroll
        for (int u = 0; u < 4; u++) {
            int nr = n0 + u*8 + grp;
            bfh[u] = *(const uint2*)&sBh[buf][nr][2*cc];
            bfl[u] = *(const uint2*)&sBl[buf][nr][2*cc];
        }
        #pragma unroll
        for (int t = 0; t < 4; t++) {
            int r0 = m0 + t*16 + grp;
            uint2 h0 = *(const uint2*)&sAh[buf][r0  ][2*cc];
            uint2 h1 = *(const uint2*)&sAh[buf][r0+8][2*cc];
            uint2 l0 = *(const uint2*)&sAl[buf][r0  ][2*cc];
            uint2 l1 = *(const uint2*)&sAl[buf][r0+8][2*cc];
            unsigned afh[4] = {h0.x, h1.x, h0.y, h1.y};
            unsigned afl[4] = {l0.x, l1.x, l0.y, l1.y};
            #pragma unroll
            for (int u = 0; u < 4; u++) {
                unsigned bh2[2] = {bfh[u].x, bfh[u].y};
                unsigned bl2[2] = {bfl[u].x, bfl[u].y};
                mma_tf32(acc[t][u], afl, bh2);   // Al*Bb
                mma_tf32(acc[t][u], afh, bl2);   // Ab*Bl
                mma_tf32(acc[t][u], afh, bh2);   // Ab*Bb
            }
        }
        if (kt < 64) {
            buf ^= 1;
            *(uint4*)&sAh[buf][sr][pp] = vah;
            *(uint4*)&sAl[buf][sr][pp] = val;
            *(uint4*)&sBh[buf][sr][pp] = vbh;
            *(uint4*)&sBl[buf][sr][pp] = vbl;
            __syncthreads();
        }
    }

    #pragma unroll
    for (int t = 0; t < 4; t++)
        #pragma unroll
        for (int u = 0; u < 4; u++) {
            int row = bm + m0 + t*16 + grp;
            int col = bn + n0 + u*8 + 2*cc;
            float2 o0 = make_float2(acc[t][u][0], acc[t][u][1]);
            float2 o1 = make_float2(acc[t][u][2], acc[t][u][3]);
            if (HASBIAS) {
                float2 bv = *(const float2*)(bias + col);
                o0.x += bv.x; o0.y += bv.y; o1.x += bv.x; o1.y += bv.y;
            }
            *(float2*)(C + (size_t)row * DD + col)       = o0;
            *(float2*)(C + (size_t)(row + 8) * DD + col) = o1;
        }
}

// ---------------- K2: LSH hashing, FFMA2 (bitwise-stable buckets) -----------
__global__ __launch_bounds__(128) void hash_kernel(const float* __restrict__ rot)
{
    __shared__ __align__(16) float qs[64][64];
    __shared__ __align__(16) float rs[64][128];
    int bh = blockIdx.y;
    int t0 = blockIdx.x * 64;
    int b = bh >> 3, h = bh & 7;
    int tid = threadIdx.x;
    int quad = tid >> 3, ig = tid & 7;

    for (int idx = tid; idx < 64*16; idx += 128) {
        int tk = idx >> 4, fq = (idx & 15) * 4;
        *(float4*)&qs[tk][fq] =
            *(const float4*)(g_qk + ((size_t)(b*NN + t0 + tk))*DD + h*DHD + fq);
    }

    for (int r = 0; r < NHASH; r++) {
        __syncthreads();
        for (int idx = tid; idx < 64*32; idx += 128) {
            int f = idx >> 5, iq = (idx & 31) * 4;
            *(float4*)&rs[f][iq] = *(const float4*)(rot + f*(NHASH*128) + r*128 + iq);
        }
        __syncthreads();

        ull acc2[4][4][2];
        #pragma unroll
        for (int tt = 0; tt < 4; tt++)
            #pragma unroll
            for (int c = 0; c < 4; c++) {
                acc2[tt][c][0] = 0ull; acc2[tt][c][1] = 0ull;
            }

        for (int f = 0; f < 64; f++) {
            ull qd[4];
            #pragma unroll
            for (int tt = 0; tt < 4; tt++) {
                float q = qs[quad*4 + tt][f];
                qd[tt] = pack2(q, q);
            }
            #pragma unroll
            for (int c = 0; c < 4; c++) {
                ulonglong2 rv = *(const ulonglong2*)&rs[f][ig*4 + c*32];
                #pragma unroll
                for (int tt = 0; tt < 4; tt++) {
                    fma2(acc2[tt][c][0], qd[tt], rv.x);
                    fma2(acc2[tt][c][1], qd[tt], rv.y);
                }
            }
        }

        #pragma unroll
        for (int tt = 0; tt < 4; tt++) {
            float bvv = -1e30f; int bi = 256;
            #pragma unroll
            for (int c = 0; c < 4; c++)
                #pragma unroll
                for (int jp = 0; jp < 2; jp++) {
                    float v0, v1;
                    unpack2(acc2[tt][c][jp], v0, v1);
                    float vv[2] = {v0, v1};
                    #pragma unroll
                    for (int u = 0; u < 2; u++) {
                        int i = ig*4 + c*32 + jp*2 + u;
                        float v = vv[u];
                        if (v > bvv || (v == bvv && i < bi)) { bvv = v; bi = i; }
                        float vn = -v; int i2 = 128 + i;
                        if (vn > bvv || (vn == bvv && i2 < bi)) { bvv = vn; bi = i2; }
                    }
                }
            #pragma unroll
            for (int m = 1; m < 8; m <<= 1) {
                float ov = __shfl_xor_sync(0xffffffffu, bvv, m);
                int   oi = __shfl_xor_sync(0xffffffffu, bi, m);
                if (ov > bvv || (ov == bvv && oi < bi)) { bvv = ov; bi = oi; }
            }
            if (ig == 0)
                g_bucket[(bh*NHASH + r)*NN + t0 + quad*4 + tt] = bi;
        }
    }
}

// ---------------- K3: stable counting sort per (bh, round) ------------------
__global__ __launch_bounds__(256) void sort_kernel()
{
    __shared__ __align__(16) int bks[NN];
    __shared__ int tmp[NN];
    __shared__ int hist[NBUCK];
    __shared__ int offs[NBUCK];
    __shared__ int cnt[NBUCK];
    __shared__ int wsum[8];
    int bhr = blockIdx.x;
    int tid = threadIdx.x;
    for (int t = tid; t < NN; t += 256) bks[t] = g_bucket[bhr*NN + t];
    hist[tid] = 0; cnt[tid] = 0;
    __syncthreads();
    for (int t = tid; t < NN; t += 256) atomicAdd(&hist[bks[t]], 1);
    __syncthreads();
    int hv = hist[tid];
    int incl = hv;
    #pragma unroll
    for (int d = 1; d < 32; d <<= 1) {
        int nv = __shfl_up_sync(0xffffffffu, incl, d);
        if ((tid & 31) >= d) incl += nv;
    }
    if ((tid & 31) == 31) wsum[tid >> 5] = incl;
    __syncthreads();
    if (tid == 0) {
        int s = 0;
        #pragma unroll
        for (int k = 0; k < 8; k++) { int t = wsum[k]; wsum[k] = s; s += t; }
    }
    __syncthreads();
    offs[tid] = incl - hv + wsum[tid >> 5];
    __syncthreads();
    for (int t = tid; t < NN; t += 256) {
        int b = bks[t];
        int p = atomicAdd(&cnt[b], 1);
        tmp[offs[b] + p] = t;
    }
    __syncthreads();
    {
        int o = offs[tid], k = hist[tid];
        for (int x = 1; x < k; x++) {
            int key = tmp[o + x];
            int y = x - 1;
            while (y >= 0 && tmp[o + y] > key) { tmp[o + y + 1] = tmp[o + y]; y--; }
            tmp[o + y + 1] = key;
        }
    }
    __syncthreads();
    for (int t = tid; t < NN; t += 256) g_st[bhr*NN + t] = tmp[t];
}

// ---------------- K4: chunked attention, lane-pair layout -------------------
__global__ __launch_bounds__(128) void attn_kernel()
{
    __shared__ __align__(16) float qs[4][4][68];
    __shared__ __align__(16) float ks[4][8][68];
    __shared__ int   tka[4][8];
    int w = threadIdx.x >> 5;
    int lane = threadIdx.x & 31;
    int C = blockIdx.x * 4 + w;
    int bh = C >> 10;
    int Cl = C & 1023;
    int r = Cl >> 8, c = Cl & 255;
    int Cp = (Cl + 1023) & 1023;
    int rp = Cp >> 8, cp = Cp & 255;
    int b = bh >> 3, h = bh & 7;

    if (lane < 4) {
        tka[w][lane]     = g_st[(bh*NHASH + r)*NN + c*BSZ + lane];
        tka[w][lane + 4] = g_st[(bh*NHASH + rp)*NN + cp*BSZ + lane];
    }
    __syncwarp();

    ull v2[8];
    #pragma unroll
    for (int j = 0; j < 8; j++) {
        int t = tka[w][j];
        const float* ksrc = g_qk + ((size_t)(b*NN + t))*DD + h*DHD;
        const float* vsrc = g_v  + ((size_t)(b*NN + t))*DD + h*DHD;
        float2 kp = *(const float2*)(ksrc + 2*lane);
        float2 vp = *(const float2*)(vsrc + 2*lane);
        v2[j] = pack2(vp.x, vp.y);
        if (j < 4) *(float2*)&qs[w][j][2*lane] = kp;
        float ss = kp.x*kp.x + kp.y*kp.y;
        #pragma unroll
        for (int d = 16; d >= 1; d >>= 1) ss += __shfl_xor_sync(0xffffffffu, ss, d);
        float scale = 1.0f / fmaxf(sqrtf(ss), 1e-6f);
        float2 kn; kn.x = kp.x * scale; kn.y = kp.y * scale;
        *(float2*)&ks[w][j][2*lane] = kn;
    }
    __syncwarp();

    int i = lane >> 3, j = lane & 7;
    const ulonglong2* q2 = (const ulonglong2*)qs[w][i];
    const ulonglong2* k2 = (const ulonglong2*)ks[w][j];
    ull d2 = 0ull;
    #pragma unroll
    for (int fq = 0; fq < 16; fq++) {
        ulonglong2 a = q2[fq], kk = k2[fq];
        fma2(d2, a.x, kk.x);
        fma2(d2, a.y, kk.y);
    }
    float dlo, dhi;
    unpack2(d2, dlo, dhi);
    float d = (dlo + dhi) * 0.125f;
    if (tka[w][i] == tka[w][j]) d = -5e4f;

    float m = d;
    #pragma unroll
    for (int dd = 4; dd >= 1; dd >>= 1) m = fmaxf(m, __shfl_xor_sync(0xffffffffu, m, dd));
    float e = expf(d - m);
    float s = e;
    #pragma unroll
    for (int dd = 4; dd >= 1; dd >>= 1) s += __shfl_xor_sync(0xffffffffu, s, dd);
    float lse = m + logf(s);
    float pval = e / s;

    #pragma unroll
    for (int it = 0; it < 4; it++) {
        ull acc = 0ull;
        #pragma unroll
        for (int jj = 0; jj < 8; jj++) {
            float p = __shfl_sync(0xffffffffu, pval, it*8 + jj);
            fma2(acc, pack2(p, p), v2[jj]);
        }
        *(ull*)&g_o[(((size_t)(bh*NHASH + r))*NN + tka[w][it])*DHD + 2*lane] = acc;
    }
    if (j == 0)
        g_logits[(bh*NHASH + r)*NN + tka[w][i]] = lse;
}

// ---------------- K5: combine rounds + merge heads + SPLIT fused ------------
// Writes the att matrix directly as tile-major tf32 hi/lo (no g_att pass).
__global__ __launch_bounds__(256) void combine_kernel(
    unsigned* __restrict__ hi, unsigned* __restrict__ lo)
{
    int bh = blockIdx.y;
    int t = blockIdx.x * 8 + (threadIdx.x >> 5);
    int fp = threadIdx.x & 31;
    int b = bh >> 3, h = bh & 7;
    float l[NHASH];
    #pragma unroll
    for (int r = 0; r < NHASH; r++) l[r] = g_logits[(bh*NHASH + r)*NN + t];
    float m = fmaxf(fmaxf(l[0], l[1]), fmaxf(l[2], l[3]));
    float s = 0.f;
    #pragma unroll
    for (int r = 0; r < NHASH; r++) s += expf(l[r] - m);
    ull acc = 0ull;
    #pragma unroll
    for (int r = 0; r < NHASH; r++) {
        float wr = expf(l[r] - m) / s;
        ull wd = pack2(wr, wr);
        ull vv = *(const ull*)&g_o[(((size_t)(bh*NHASH + r))*NN + t)*DHD + fp*2];
        fma2(acc, wd, vv);
    }
    // fused split: features (2fp, 2fp+1) of column h*64 -> tile-major hi/lo
    float a0, a1;
    unpack2(acc, a0, a1);
    int kg  = h*8 + (fp >> 2);            // k-group (column/8)
    int kw  = (2*fp) & 7;                 // even local k
    int p0  = 2*(kw & 3) + (kw >> 2);     // perm pos of kw
    int p1  = 2*((kw+1) & 3) + ((kw+1) >> 2);
    int row = b*NN + t;
    size_t off = ((size_t)kg * MTOT + row) * 8;
    unsigned h0, l0, h1, l1;
    tf32_split(a0, h0, l0);
    tf32_split(a1, h1, l1);
    hi[off + p0] = h0; lo[off + p0] = l0;
    hi[off + p1] = h1; lo[off + p1] = l1;
}

// ---------------- launch ----------------------------------------------------
extern "C" void kernel_launch(void* const* d_in, const int* in_sizes, int n_in,
                              void* d_out, int out_size)
{
    (void)in_sizes; (void)n_in; (void)out_size;
    const float* queries = (const float*)d_in[0];
    const float* Wqk  = (const float*)d_in[3];
    const float* Wv   = (const float*)d_in[4];
    const float* Wout = (const float*)d_in[5];
    const float* bout = (const float*)d_in[6];
    const float* rot  = (const float*)d_in[7];
    float* out = (float*)d_out;

    float *qk, *v;
    unsigned *sh, *sl, *wvh, *wvl, *woh, *wol;
    cudaGetSymbolAddress((void**)&qk,  g_qk);
    cudaGetSymbolAddress((void**)&v,   g_v);
    cudaGetSymbolAddress((void**)&sh,  g_sh);
    cudaGetSymbolAddress((void**)&sl,  g_sl);
    cudaGetSymbolAddress((void**)&wvh, g_wvh);
    cudaGetSymbolAddress((void**)&wvl, g_wvl);
    cudaGetSymbolAddress((void**)&woh, g_woh);
    cudaGetSymbolAddress((void**)&wol, g_wol);

    dim3 ggrid(DD/128, MTOT/128);   // (4, 64)
    // prep splits (weights + queries)
    split_w<<<DD*64/256, 256>>>(Wv,   wvh, wvl);
    split_w<<<DD*64/256, 256>>>(Wout, woh, wol);
    split_rows<<<MTOT*64/256, 256>>>(queries, sh, sl);
    // qk GEMM: EXACT fp32 FFMA2 (bucket decisions must not perturb)
    sgemm128<false><<<ggrid, 256>>>(queries, Wqk, nullptr, qk, MTOT, DD, DD);
    hash_kernel<<<dim3(NN/64, BHN), 128>>>(rot);
    sort_kernel<<<BHN*NHASH, 256>>>();
    // v GEMM on tensor cores (3xTF32, tile-major, double-buffered)
    gemm_tc<false><<<ggrid, 256>>>(sh, sl, wvh, wvl, nullptr, v);
    attn_kernel<<<(BHN*CHTOT)/4, 128>>>();
    // combine writes split att directly (reuses sh/sl)
    combine_kernel<<<dim3(NN/8, BHN), 256>>>(sh, sl);
    // output GEMM + bias
    gemm_tc<true><<<ggrid, 256>>>(sh, sl, woh, wol, bout, out);
}

// round 16
// speedup vs baseline: 1.1242x; 1.0436x over previous
#include <cuda_runtime.h>
#include <math.h>

// ---------------- problem constants ----------------
#define BN     8
#define NN     1024
#define DD     512
#define HH     8
#define DHD    64
#define NHASH  4
#define NBUCK  256
#define BSZ    4
#define BHN    (BN*HH)
#define MTOT   (BN*NN)
#define CHTOT  (NHASH*NBUCK)

typedef unsigned long long ull;

// ---- packed f32x2 helpers (FFMA2; bit-exact fp32, 2 lanes/instr) -----------
__device__ __forceinline__ ull pack2(float lo, float hi) {
    ull r; asm("mov.b64 %0, {%1, %2};" : "=l"(r) : "f"(lo), "f"(hi)); return r;
}
__device__ __forceinline__ void unpack2(ull v, float& lo, float& hi) {
    asm("mov.b64 {%0, %1}, %2;" : "=f"(lo), "=f"(hi) : "l"(v));
}
__device__ __forceinline__ void fma2(ull& d, ull a, ull b) {
    asm("fma.rn.f32x2 %0, %1, %2, %0;" : "+l"(d) : "l"(a), "l"(b));
}

// ---- 3xTF32 helpers --------------------------------------------------------
__device__ __forceinline__ void tf32_split(float x, unsigned& hi, unsigned& lo) {
    unsigned h; asm("cvt.rna.tf32.f32 %0, %1;" : "=r"(h) : "f"(x));
    float r = x - __uint_as_float(h);
    unsigned l; asm("cvt.rna.tf32.f32 %0, %1;" : "=r"(l) : "f"(r));
    hi = h; lo = l;
}
__device__ __forceinline__ void mma_tf32(float* c, const unsigned* a, const unsigned* b) {
    asm volatile("mma.sync.aligned.m16n8k8.row.col.f32.tf32.tf32.f32 "
        "{%0,%1,%2,%3}, {%4,%5,%6,%7}, {%8,%9}, {%0,%1,%2,%3};"
        : "+f"(c[0]), "+f"(c[1]), "+f"(c[2]), "+f"(c[3])
        : "r"(a[0]), "r"(a[1]), "r"(a[2]), "r"(a[3]), "r"(b[0]), "r"(b[1]));
}

// ---------------- scratch ---------------------------------------------------
__device__ float    g_qk    [BN*NN*DD];
__device__ float    g_v     [BN*NN*DD];
__device__ int      g_bucket[BHN*NHASH*NN];
__device__ int      g_st    [BHN*NHASH*NN];
__device__ float    g_o     [(size_t)BHN*NHASH*NN*DHD];
__device__ float    g_logits[BHN*NHASH*NN];
// pre-split tf32 operands, TILE-MAJOR layout:
//   A: ((kt*MTOT + row)*8 + p),  B: ((kt*DD + n)*8 + p),  kt = k/8, p = perm pos
__device__ unsigned g_sh [MTOT*DD];
__device__ unsigned g_sl [MTOT*DD];
__device__ unsigned g_wvh[DD*DD];
__device__ unsigned g_wvl[DD*DD];
__device__ unsigned g_woh[DD*DD];
__device__ unsigned g_wol[DD*DD];

// perm within a k8 group: pos p holds k = (p>>1) + 4*(p&1); inverse p(k) = 2*(k&3)+(k>>2)

// ---------------- prep: split rows [rows][512] -> tile-major hi/lo ----------
__global__ __launch_bounds__(256) void split_rows(
    const float* __restrict__ src, unsigned* __restrict__ hi, unsigned* __restrict__ lo)
{
    int id = blockIdx.x * 256 + threadIdx.x;      // MTOT*64 threads
    int kg = id >> 13, row = id & (MTOT - 1);     // MTOT = 8192 = 2^13
    const float* s = src + (size_t)row * DD + kg * 8;
    float4 v0 = *(const float4*)s;
    float4 v1 = *(const float4*)(s + 4);
    float f[8] = {v0.x, v0.y, v0.z, v0.w, v1.x, v1.y, v1.z, v1.w};
    unsigned oh[8], ol[8];
    #pragma unroll
    for (int p = 0; p < 8; p++) {
        int k = (p >> 1) + 4 * (p & 1);
        tf32_split(f[k], oh[p], ol[p]);
    }
    size_t off = ((size_t)kg * MTOT + row) * 8;
    *(uint4*)(hi + off)     = make_uint4(oh[0], oh[1], oh[2], oh[3]);
    *(uint4*)(hi + off + 4) = make_uint4(oh[4], oh[5], oh[6], oh[7]);
    *(uint4*)(lo + off)     = make_uint4(ol[0], ol[1], ol[2], ol[3]);
    *(uint4*)(lo + off + 4) = make_uint4(ol[4], ol[5], ol[6], ol[7]);
}

// ---------------- prep: split W[k][n] -> tile-major [kt][n][perm8] hi/lo ----
__global__ __launch_bounds__(256) void split_w(
    const float* __restrict__ w, unsigned* __restrict__ hi, unsigned* __restrict__ lo)
{
    int id = blockIdx.x * 256 + threadIdx.x;      // 64*512 threads
    int kg = id >> 9, n = id & 511;
    float f[8];
    #pragma unroll
    for (int kw = 0; kw < 8; kw++)
        f[kw] = w[(size_t)(kg * 8 + kw) * DD + n];
    unsigned oh[8], ol[8];
    #pragma unroll
    for (int p = 0; p < 8; p++) {
        int k = (p >> 1) + 4 * (p & 1);
        tf32_split(f[k], oh[p], ol[p]);
    }
    size_t off = ((size_t)kg * DD + n) * 8;
    *(uint4*)(hi + off)     = make_uint4(oh[0], oh[1], oh[2], oh[3]);
    *(uint4*)(hi + off + 4) = make_uint4(oh[4], oh[5], oh[6], oh[7]);
    *(uint4*)(lo + off)     = make_uint4(ol[0], ol[1], ol[2], ol[3]);
    *(uint4*)(lo + off + 4) = make_uint4(ol[4], ol[5], ol[6], ol[7]);
}

// ---------------- smem overlays for the fused kernel ------------------------
struct SgemmSmem { float As[2][8][132]; float Bs[2][8][132]; };      // 16896 B
struct TcSmem { unsigned sAh[2][128][8], sAl[2][128][8],
                         sBh[2][128][8], sBl[2][128][8]; };          // 32768 B

// ---- sgemm body (EXACT fp32 FFMA2; identical math to proven R6 kernel) -----
__device__ __forceinline__ void sgemm_body(
    SgemmSmem* sm, const float* __restrict__ A, const float* __restrict__ Bm,
    float* __restrict__ C, int bm, int bn)
{
    const int K = DD, Nn = DD;
    int tid = threadIdx.x;
    int ty = tid >> 4, tx = tid & 15;
    int arow = tid >> 1;
    int akq  = (tid & 1) * 4;
    int bk   = tid >> 5;
    int bnq  = (tid & 31) * 4;

    const float* Aptr = A  + (size_t)(bm + arow) * K + akq;
    const float* Bptr = Bm + (size_t)bk * Nn + bn + bnq;

    ull acc[8][4];
    #pragma unroll
    for (int i = 0; i < 8; i++)
        #pragma unroll
        for (int jp = 0; jp < 4; jp++) acc[i][jp] = 0ull;

    float4 av = *(const float4*)(Aptr);
    float4 bv = *(const float4*)(Bptr);
    sm->As[0][akq+0][arow] = av.x;
    sm->As[0][akq+1][arow] = av.y;
    sm->As[0][akq+2][arow] = av.z;
    sm->As[0][akq+3][arow] = av.w;
    *(float4*)&sm->Bs[0][bk][bnq] = bv;
    __syncthreads();

    int buf = 0;
    for (int k0 = 8; k0 <= K; k0 += 8) {
        if (k0 < K) {
            av = *(const float4*)(Aptr + k0);
            bv = *(const float4*)(Bptr + (size_t)k0 * Nn);
        }
        #pragma unroll
        for (int k = 0; k < 8; k++) {
            float4 a0 = *(const float4*)&sm->As[buf][k][ty*4];
            float4 a1 = *(const float4*)&sm->As[buf][k][64 + ty*4];
            ulonglong2 b0 = *(const ulonglong2*)&sm->Bs[buf][k][tx*4];
            ulonglong2 b1 = *(const ulonglong2*)&sm->Bs[buf][k][64 + tx*4];
            ull ad[8];
            ad[0] = pack2(a0.x, a0.x); ad[1] = pack2(a0.y, a0.y);
            ad[2] = pack2(a0.z, a0.z); ad[3] = pack2(a0.w, a0.w);
            ad[4] = pack2(a1.x, a1.x); ad[5] = pack2(a1.y, a1.y);
            ad[6] = pack2(a1.z, a1.z); ad[7] = pack2(a1.w, a1.w);
            #pragma unroll
            for (int i = 0; i < 8; i++) {
                fma2(acc[i][0], ad[i], b0.x);
                fma2(acc[i][1], ad[i], b0.y);
                fma2(acc[i][2], ad[i], b1.x);
                fma2(acc[i][3], ad[i], b1.y);
            }
        }
        if (k0 < K) {
            buf ^= 1;
            sm->As[buf][akq+0][arow] = av.x;
            sm->As[buf][akq+1][arow] = av.y;
            sm->As[buf][akq+2][arow] = av.z;
            sm->As[buf][akq+3][arow] = av.w;
            *(float4*)&sm->Bs[buf][bk][bnq] = bv;
            __syncthreads();
        }
    }

    #pragma unroll
    for (int rh = 0; rh < 2; rh++)
        #pragma unroll
        for (int i = 0; i < 4; i++) {
            int row = bm + rh*64 + ty*4 + i;
            #pragma unroll
            for (int ch = 0; ch < 2; ch++) {
                float4 o;
                unpack2(acc[rh*4+i][ch*2+0], o.x, o.y);
                unpack2(acc[rh*4+i][ch*2+1], o.z, o.w);
                int col = bn + ch*64 + tx*4;
                *(float4*)(C + (size_t)row * Nn + col) = o;
            }
        }
}

// ---- gemm_tc body (3xTF32, tile-major, double-buffered; identical to R15) --
template<bool HASBIAS>
__device__ __forceinline__ void gemm_tc_body(
    TcSmem* sm,
    const unsigned* __restrict__ Ahg, const unsigned* __restrict__ Alg,
    const unsigned* __restrict__ Bhg, const unsigned* __restrict__ Blg,
    const float* __restrict__ bias, float* __restrict__ C, int bm, int bn)
{
    int tid = threadIdx.x;
    int wid = tid >> 5, lane = tid & 31;
    int m0 = (wid >> 2) * 64, n0 = (wid & 3) * 32;
    int grp = lane >> 2, cc = lane & 3;

    int sr = tid >> 1, pp = (tid & 1) * 4;
    const unsigned* pAh = Ahg + ((size_t)(bm + sr)) * 8 + pp;
    const unsigned* pAl = Alg + ((size_t)(bm + sr)) * 8 + pp;
    const unsigned* pBh = Bhg + ((size_t)(bn + sr)) * 8 + pp;
    const unsigned* pBl = Blg + ((size_t)(bn + sr)) * 8 + pp;

    float acc[4][4][4];
    #pragma unroll
    for (int t = 0; t < 4; t++)
        #pragma unroll
        for (int u = 0; u < 4; u++)
            #pragma unroll
            for (int x = 0; x < 4; x++) acc[t][u][x] = 0.f;

    uint4 vah = *(const uint4*)(pAh);
    uint4 val = *(const uint4*)(pAl);
    uint4 vbh = *(const uint4*)(pBh);
    uint4 vbl = *(const uint4*)(pBl);
    *(uint4*)&sm->sAh[0][sr][pp] = vah;
    *(uint4*)&sm->sAl[0][sr][pp] = val;
    *(uint4*)&sm->sBh[0][sr][pp] = vbh;
    *(uint4*)&sm->sBl[0][sr][pp] = vbl;
    __syncthreads();

    int buf = 0;
    for (int kt = 1; kt <= 64; kt++) {
        if (kt < 64) {
            vah = *(const uint4*)(pAh + (size_t)kt * MTOT * 8);
            val = *(const uint4*)(pAl + (size_t)kt * MTOT * 8);
            vbh = *(const uint4*)(pBh + (size_t)kt * DD * 8);
            vbl = *(const uint4*)(pBl + (size_t)kt * DD * 8);
        }
        uint2 bfh[4], bfl[4];
        #pragma unroll
        for (int u = 0; u < 4; u++) {
            int nr = n0 + u*8 + grp;
            bfh[u] = *(const uint2*)&sm->sBh[buf][nr][2*cc];
            bfl[u] = *(const uint2*)&sm->sBl[buf][nr][2*cc];
        }
        #pragma unroll
        for (int t = 0; t < 4; t++) {
            int r0 = m0 + t*16 + grp;
            uint2 h0 = *(const uint2*)&sm->sAh[buf][r0  ][2*cc];
            uint2 h1 = *(const uint2*)&sm->sAh[buf][r0+8][2*cc];
            uint2 l0 = *(const uint2*)&sm->sAl[buf][r0  ][2*cc];
            uint2 l1 = *(const uint2*)&sm->sAl[buf][r0+8][2*cc];
            unsigned afh[4] = {h0.x, h1.x, h0.y, h1.y};
            unsigned afl[4] = {l0.x, l1.x, l0.y, l1.y};
            #pragma unroll
            for (int u = 0; u < 4; u++) {
                unsigned bh2[2] = {bfh[u].x, bfh[u].y};
                unsigned bl2[2] = {bfl[u].x, bfl[u].y};
                mma_tf32(acc[t][u], afl, bh2);   // Al*Bb
                mma_tf32(acc[t][u], afh, bl2);   // Ab*Bl
                mma_tf32(acc[t][u], afh, bh2);   // Ab*Bb
            }
        }
        if (kt < 64) {
            buf ^= 1;
            *(uint4*)&sm->sAh[buf][sr][pp] = vah;
            *(uint4*)&sm->sAl[buf][sr][pp] = val;
            *(uint4*)&sm->sBh[buf][sr][pp] = vbh;
            *(uint4*)&sm->sBl[buf][sr][pp] = vbl;
            __syncthreads();
        }
    }

    #pragma unroll
    for (int t = 0; t < 4; t++)
        #pragma unroll
        for (int u = 0; u < 4; u++) {
            int row = bm + m0 + t*16 + grp;
            int col = bn + n0 + u*8 + 2*cc;
            float2 o0 = make_float2(acc[t][u][0], acc[t][u][1]);
            float2 o1 = make_float2(acc[t][u][2], acc[t][u][3]);
            if (HASBIAS) {
                float2 bv = *(const float2*)(bias + col);
                o0.x += bv.x; o0.y += bv.y; o1.x += bv.x; o1.y += bv.y;
            }
            *(float2*)(C + (size_t)row * DD + col)       = o0;
            *(float2*)(C + (size_t)(row + 8) * DD + col) = o1;
        }
}

// ---------------- fused qk-SGEMM + v-gemm_tc (pipe overlap) -----------------
// grid (2, 4, 64): x = role (fastest-varying -> roles interleave across SMs),
// y = n-tile, z = m-tile. Both bodies identical to their proven standalone
// versions -> outputs bitwise unchanged.
__global__ __launch_bounds__(256, 2) void fused_qkv(
    const float* __restrict__ A, const float* __restrict__ Wqk,
    float* __restrict__ Cq,
    const unsigned* __restrict__ Ahg, const unsigned* __restrict__ Alg,
    const unsigned* __restrict__ Bhg, const unsigned* __restrict__ Blg,
    float* __restrict__ Cv)
{
    __shared__ __align__(16) char smemraw[sizeof(TcSmem)];
    int bm = blockIdx.z * 128, bn = blockIdx.y * 128;
    if (blockIdx.x == 0)
        sgemm_body((SgemmSmem*)smemraw, A, Wqk, Cq, bm, bn);
    else
        gemm_tc_body<false>((TcSmem*)smemraw, Ahg, Alg, Bhg, Blg, nullptr, Cv, bm, bn);
}

// ---------------- standalone gemm_tc (output GEMM + bias) -------------------
template<bool HASBIAS>
__global__ __launch_bounds__(256, 2) void gemm_tc(
    const unsigned* __restrict__ Ahg, const unsigned* __restrict__ Alg,
    const unsigned* __restrict__ Bhg, const unsigned* __restrict__ Blg,
    const float* __restrict__ bias, float* __restrict__ C)
{
    __shared__ __align__(16) char smemraw[sizeof(TcSmem)];
    gemm_tc_body<HASBIAS>((TcSmem*)smemraw, Ahg, Alg, Bhg, Blg, bias, C,
                          blockIdx.y * 128, blockIdx.x * 128);
}

// ---------------- K2: LSH hashing, FFMA2 (bitwise-stable buckets) -----------
__global__ __launch_bounds__(128) void hash_kernel(const float* __restrict__ rot)
{
    __shared__ __align__(16) float qs[64][64];
    __shared__ __align__(16) float rs[64][128];
    int bh = blockIdx.y;
    int t0 = blockIdx.x * 64;
    int b = bh >> 3, h = bh & 7;
    int tid = threadIdx.x;
    int quad = tid >> 3, ig = tid & 7;

    for (int idx = tid; idx < 64*16; idx += 128) {
        int tk = idx >> 4, fq = (idx & 15) * 4;
        *(float4*)&qs[tk][fq] =
            *(const float4*)(g_qk + ((size_t)(b*NN + t0 + tk))*DD + h*DHD + fq);
    }

    for (int r = 0; r < NHASH; r++) {
        __syncthreads();
        for (int idx = tid; idx < 64*32; idx += 128) {
            int f = idx >> 5, iq = (idx & 31) * 4;
            *(float4*)&rs[f][iq] = *(const float4*)(rot + f*(NHASH*128) + r*128 + iq);
        }
        __syncthreads();

        ull acc2[4][4][2];
        #pragma unroll
        for (int tt = 0; tt < 4; tt++)
            #pragma unroll
            for (int c = 0; c < 4; c++) {
                acc2[tt][c][0] = 0ull; acc2[tt][c][1] = 0ull;
            }

        for (int f = 0; f < 64; f++) {
            ull qd[4];
            #pragma unroll
            for (int tt = 0; tt < 4; tt++) {
                float q = qs[quad*4 + tt][f];
                qd[tt] = pack2(q, q);
            }
            #pragma unroll
            for (int c = 0; c < 4; c++) {
                ulonglong2 rv = *(const ulonglong2*)&rs[f][ig*4 + c*32];
                #pragma unroll
                for (int tt = 0; tt < 4; tt++) {
                    fma2(acc2[tt][c][0], qd[tt], rv.x);
                    fma2(acc2[tt][c][1], qd[tt], rv.y);
                }
            }
        }

        #pragma unroll
        for (int tt = 0; tt < 4; tt++) {
            float bvv = -1e30f; int bi = 256;
            #pragma unroll
            for (int c = 0; c < 4; c++)
                #pragma unroll
                for (int jp = 0; jp < 2; jp++) {
                    float v0, v1;
                    unpack2(acc2[tt][c][jp], v0, v1);
                    float vv[2] = {v0, v1};
                    #pragma unroll
                    for (int u = 0; u < 2; u++) {
                        int i = ig*4 + c*32 + jp*2 + u;
                        float v = vv[u];
                        if (v > bvv || (v == bvv && i < bi)) { bvv = v; bi = i; }
                        float vn = -v; int i2 = 128 + i;
                        if (vn > bvv || (vn == bvv && i2 < bi)) { bvv = vn; bi = i2; }
                    }
                }
            #pragma unroll
            for (int m = 1; m < 8; m <<= 1) {
                float ov = __shfl_xor_sync(0xffffffffu, bvv, m);
                int   oi = __shfl_xor_sync(0xffffffffu, bi, m);
                if (ov > bvv || (ov == bvv && oi < bi)) { bvv = ov; bi = oi; }
            }
            if (ig == 0)
                g_bucket[(bh*NHASH + r)*NN + t0 + quad*4 + tt] = bi;
        }
    }
}

// ---------------- K3: stable counting sort per (bh, round) ------------------
__global__ __launch_bounds__(256) void sort_kernel()
{
    __shared__ __align__(16) int bks[NN];
    __shared__ int tmp[NN];
    __shared__ int hist[NBUCK];
    __shared__ int offs[NBUCK];
    __shared__ int cnt[NBUCK];
    __shared__ int wsum[8];
    int bhr = blockIdx.x;
    int tid = threadIdx.x;
    for (int t = tid; t < NN; t += 256) bks[t] = g_bucket[bhr*NN + t];
    hist[tid] = 0; cnt[tid] = 0;
    __syncthreads();
    for (int t = tid; t < NN; t += 256) atomicAdd(&hist[bks[t]], 1);
    __syncthreads();
    int hv = hist[tid];
    int incl = hv;
    #pragma unroll
    for (int d = 1; d < 32; d <<= 1) {
        int nv = __shfl_up_sync(0xffffffffu, incl, d);
        if ((tid & 31) >= d) incl += nv;
    }
    if ((tid & 31) == 31) wsum[tid >> 5] = incl;
    __syncthreads();
    if (tid == 0) {
        int s = 0;
        #pragma unroll
        for (int k = 0; k < 8; k++) { int t = wsum[k]; wsum[k] = s; s += t; }
    }
    __syncthreads();
    offs[tid] = incl - hv + wsum[tid >> 5];
    __syncthreads();
    for (int t = tid; t < NN; t += 256) {
        int b = bks[t];
        int p = atomicAdd(&cnt[b], 1);
        tmp[offs[b] + p] = t;
    }
    __syncthreads();
    {
        int o = offs[tid], k = hist[tid];
        for (int x = 1; x < k; x++) {
            int key = tmp[o + x];
            int y = x - 1;
            while (y >= 0 && tmp[o + y] > key) { tmp[o + y + 1] = tmp[o + y]; y--; }
            tmp[o + y + 1] = key;
        }
    }
    __syncthreads();
    for (int t = tid; t < NN; t += 256) g_st[bhr*NN + t] = tmp[t];
}

// ---------------- K4: chunked attention, lane-pair layout -------------------
__global__ __launch_bounds__(128) void attn_kernel()
{
    __shared__ __align__(16) float qs[4][4][68];
    __shared__ __align__(16) float ks[4][8][68];
    __shared__ int   tka[4][8];
    int w = threadIdx.x >> 5;
    int lane = threadIdx.x & 31;
    int C = blockIdx.x * 4 + w;
    int bh = C >> 10;
    int Cl = C & 1023;
    int r = Cl >> 8, c = Cl & 255;
    int Cp = (Cl + 1023) & 1023;
    int rp = Cp >> 8, cp = Cp & 255;
    int b = bh >> 3, h = bh & 7;

    if (lane < 4) {
        tka[w][lane]     = g_st[(bh*NHASH + r)*NN + c*BSZ + lane];
        tka[w][lane + 4] = g_st[(bh*NHASH + rp)*NN + cp*BSZ + lane];
    }
    __syncwarp();

    ull v2[8];
    #pragma unroll
    for (int j = 0; j < 8; j++) {
        int t = tka[w][j];
        const float* ksrc = g_qk + ((size_t)(b*NN + t))*DD + h*DHD;
        const float* vsrc = g_v  + ((size_t)(b*NN + t))*DD + h*DHD;
        float2 kp = *(const float2*)(ksrc + 2*lane);
        float2 vp = *(const float2*)(vsrc + 2*lane);
        v2[j] = pack2(vp.x, vp.y);
        if (j < 4) *(float2*)&qs[w][j][2*lane] = kp;
        float ss = kp.x*kp.x + kp.y*kp.y;
        #pragma unroll
        for (int d = 16; d >= 1; d >>= 1) ss += __shfl_xor_sync(0xffffffffu, ss, d);
        float scale = 1.0f / fmaxf(sqrtf(ss), 1e-6f);
        float2 kn; kn.x = kp.x * scale; kn.y = kp.y * scale;
        *(float2*)&ks[w][j][2*lane] = kn;
    }
    __syncwarp();

    int i = lane >> 3, j = lane & 7;
    const ulonglong2* q2 = (const ulonglong2*)qs[w][i];
    const ulonglong2* k2 = (const ulonglong2*)ks[w][j];
    ull d2 = 0ull;
    #pragma unroll
    for (int fq = 0; fq < 16; fq++) {
        ulonglong2 a = q2[fq], kk = k2[fq];
        fma2(d2, a.x, kk.x);
        fma2(d2, a.y, kk.y);
    }
    float dlo, dhi;
    unpack2(d2, dlo, dhi);
    float d = (dlo + dhi) * 0.125f;
    if (tka[w][i] == tka[w][j]) d = -5e4f;

    float m = d;
    #pragma unroll
    for (int dd = 4; dd >= 1; dd >>= 1) m = fmaxf(m, __shfl_xor_sync(0xffffffffu, m, dd));
    float e = expf(d - m);
    float s = e;
    #pragma unroll
    for (int dd = 4; dd >= 1; dd >>= 1) s += __shfl_xor_sync(0xffffffffu, s, dd);
    float lse = m + logf(s);
    float pval = e / s;

    #pragma unroll
    for (int it = 0; it < 4; it++) {
        ull acc = 0ull;
        #pragma unroll
        for (int jj = 0; jj < 8; jj++) {
            float p = __shfl_sync(0xffffffffu, pval, it*8 + jj);
            fma2(acc, pack2(p, p), v2[jj]);
        }
        *(ull*)&g_o[(((size_t)(bh*NHASH + r))*NN + tka[w][it])*DHD + 2*lane] = acc;
    }
    if (j == 0)
        g_logits[(bh*NHASH + r)*NN + tka[w][i]] = lse;
}

// ---------------- K5: combine rounds + merge heads + SPLIT fused ------------
__global__ __launch_bounds__(256) void combine_kernel(
    unsigned* __restrict__ hi, unsigned* __restrict__ lo)
{
    int bh = blockIdx.y;
    int t = blockIdx.x * 8 + (threadIdx.x >> 5);
    int fp = threadIdx.x & 31;
    int b = bh >> 3, h = bh & 7;
    float l[NHASH];
    #pragma unroll
    for (int r = 0; r < NHASH; r++) l[r] = g_logits[(bh*NHASH + r)*NN + t];
    float m = fmaxf(fmaxf(l[0], l[1]), fmaxf(l[2], l[3]));
    float s = 0.f;
    #pragma unroll
    for (int r = 0; r < NHASH; r++) s += expf(l[r] - m);
    ull acc = 0ull;
    #pragma unroll
    for (int r = 0; r < NHASH; r++) {
        float wr = expf(l[r] - m) / s;
        ull wd = pack2(wr, wr);
        ull vv = *(const ull*)&g_o[(((size_t)(bh*NHASH + r))*NN + t)*DHD + fp*2];
        fma2(acc, wd, vv);
    }
    float a0, a1;
    unpack2(acc, a0, a1);
    int kg  = h*8 + (fp >> 2);
    int kw  = (2*fp) & 7;
    int p0  = 2*(kw & 3) + (kw >> 2);
    int p1  = 2*((kw+1) & 3) + ((kw+1) >> 2);
    int row = b*NN + t;
    size_t off = ((size_t)kg * MTOT + row) * 8;
    unsigned h0, l0, h1, l1;
    tf32_split(a0, h0, l0);
    tf32_split(a1, h1, l1);
    hi[off + p0] = h0; lo[off + p0] = l0;
    hi[off + p1] = h1; lo[off + p1] = l1;
}

// ---------------- launch ----------------------------------------------------
extern "C" void kernel_launch(void* const* d_in, const int* in_sizes, int n_in,
                              void* d_out, int out_size)
{
    (void)in_sizes; (void)n_in; (void)out_size;
    const float* queries = (const float*)d_in[0];
    const float* Wqk  = (const float*)d_in[3];
    const float* Wv   = (const float*)d_in[4];
    const float* Wout = (const float*)d_in[5];
    const float* bout = (const float*)d_in[6];
    const float* rot  = (const float*)d_in[7];
    float* out = (float*)d_out;

    float *qk, *v;
    unsigned *sh, *sl, *wvh, *wvl, *woh, *wol;
    cudaGetSymbolAddress((void**)&qk,  g_qk);
    cudaGetSymbolAddress((void**)&v,   g_v);
    cudaGetSymbolAddress((void**)&sh,  g_sh);
    cudaGetSymbolAddress((void**)&sl,  g_sl);
    cudaGetSymbolAddress((void**)&wvh, g_wvh);
    cudaGetSymbolAddress((void**)&wvl, g_wvl);
    cudaGetSymbolAddress((void**)&woh, g_woh);
    cudaGetSymbolAddress((void**)&wol, g_wol);

    // prep splits (weights + queries)
    split_w<<<DD*64/256, 256>>>(Wv,   wvh, wvl);
    split_w<<<DD*64/256, 256>>>(Wout, woh, wol);
    split_rows<<<MTOT*64/256, 256>>>(queries, sh, sl);
    // fused: exact-fp32 qk SGEMM (role 0) + 3xTF32 v GEMM (role 1), one wave mix
    fused_qkv<<<dim3(2, 4, 64), 256>>>(queries, Wqk, qk, sh, sl, wvh, wvl, v);
    hash_kernel<<<dim3(NN/64, BHN), 128>>>(rot);
    sort_kernel<<<BHN*NHASH, 256>>>();
    attn_kernel<<<(BHN*CHTOT)/4, 128>>>();
    // combine writes split att directly (reuses sh/sl)
    combine_kernel<<<dim3(NN/8, BHN), 256>>>(sh, sl);
    // output GEMM + bias
    gemm_tc<true><<<dim3(DD/128, MTOT/128), 256>>>(sh, sl, woh, wol, bout, out);
}